// round 2
// baseline (speedup 1.0000x reference)
#include <cuda_runtime.h>
#include <math.h>

#define N_B 4
#define L_S 4096
#define EMB 128
#define H_N 4
#define D_H 32
#define BM 64
#define BN 64
#define INV_SCALE 0.08838834764831845f          /* 1/sqrt(128) */
#define MASKED_LOGIT (-1e20f * 0.08838834764831845f)

// ---------------- scratch (static device allocs only) ----------------
__device__ float g_Q[N_B*H_N*L_S*D_H];          // 8 MB, [nh][l][d]
__device__ float g_K[N_B*H_N*L_S*D_H];
__device__ float g_V[N_B*H_N*L_S*D_H];
__device__ float g_O[N_B*H_N*L_S*D_H];
__device__ float g_rowmax[N_B*H_N*L_S];
__device__ float g_rowsum[N_B*H_N*L_S];
__device__ float g_logits[(size_t)N_B*H_N*L_S*L_S];   // 1.07 GB staging

// ---------------- kernel 1: per-head input projections ----------------
__global__ __launch_bounds__(256) void proj_kernel(
    const float* __restrict__ vin, const float* __restrict__ kin,
    const float* __restrict__ qin,
    const float* __restrict__ Wv, const float* __restrict__ Wk,
    const float* __restrict__ Wq)
{
    __shared__ float Ws[3][D_H*D_H];
    int t = threadIdx.x;
    for (int i = t; i < D_H*D_H; i += 256) {
        Ws[0][i] = Wq[i]; Ws[1][i] = Wk[i]; Ws[2][i] = Wv[i];
    }
    __syncthreads();

    int gid = blockIdx.x * 256 + t;             // one (n,l,h) per thread
    int h  = gid & (H_N-1);
    int nl = gid >> 2;                          // n*L + l
    int n  = nl >> 12;
    int l  = nl & (L_S-1);
    size_t inbase  = (size_t)nl * EMB + h * D_H;
    size_t outbase = (((size_t)(n*H_N + h)) * L_S + l) * D_H;

    const float* ins[3]  = {qin, kin, vin};
    float*       outs[3] = {g_Q, g_K, g_V};

    for (int mm = 0; mm < 3; mm++) {
        float x[D_H];
        #pragma unroll
        for (int i = 0; i < D_H/4; i++)
            *(float4*)&x[i*4] = *(const float4*)&ins[mm][inbase + i*4];
        #pragma unroll 4
        for (int e = 0; e < D_H; e++) {
            float a = 0.f;
            #pragma unroll
            for (int d = 0; d < D_H; d++) a += x[d] * Ws[mm][e*D_H + d];
            outs[mm][outbase + e] = a;
        }
    }
}

// ------- kernel 2: S = QK^T, mask+scale, stage logits, online (m,s) -------
__global__ __launch_bounds__(256) void scores_kernel(const int* __restrict__ mask)
{
    __shared__ float Qs[D_H][BM+4];             // transposed + pad (68)
    __shared__ float Ks[D_H][BN+4];
    int t   = threadIdx.x;
    int nh  = blockIdx.y;                       // n*H + h
    int n   = nh >> 2;
    int qr0 = blockIdx.x * BM;

    const float* Qg   = g_Q + (size_t)nh * L_S * D_H;
    const float* Kg   = g_K + (size_t)nh * L_S * D_H;
    float*       Lg   = g_logits + (size_t)nh * L_S * L_S;
    const int*   mrow = mask + n * L_S;

    for (int idx = t; idx < BM*D_H; idx += 256) {
        int r = idx >> 5, d = idx & 31;
        Qs[d][r] = Qg[(size_t)(qr0 + r)*D_H + d];
    }

    int tx = t & 15;                            // key group (4 cols)
    int ty = t >> 4;                            // row group (4 rows)
    float m[4], s[4];
    #pragma unroll
    for (int i = 0; i < 4; i++) { m[i] = -INFINITY; s[i] = 0.f; }

    for (int kt = 0; kt < L_S/BN; kt++) {
        __syncthreads();                        // protect Ks / first-iter Qs
        for (int idx = t; idx < BN*D_H; idx += 256) {
            int r = idx >> 5, d = idx & 31;
            Ks[d][r] = Kg[(size_t)(kt*BN + r)*D_H + d];
        }
        __syncthreads();

        float acc[4][4];
        #pragma unroll
        for (int i = 0; i < 4; i++)
            #pragma unroll
            for (int j = 0; j < 4; j++) acc[i][j] = 0.f;

        #pragma unroll
        for (int d = 0; d < D_H; d++) {
            float4 q = *(float4*)&Qs[d][ty*4];
            float4 k = *(float4*)&Ks[d][tx*4];
            float qa[4] = {q.x,q.y,q.z,q.w};
            float ka[4] = {k.x,k.y,k.z,k.w};
            #pragma unroll
            for (int i = 0; i < 4; i++)
                #pragma unroll
                for (int j = 0; j < 4; j++) acc[i][j] += qa[i]*ka[j];
        }

        int kbase = kt*BN + tx*4;
        int4 mv = *(const int4*)&mrow[kbase];
        int mva[4] = {mv.x, mv.y, mv.z, mv.w};
        #pragma unroll
        for (int i = 0; i < 4; i++) {
            float l0 = mva[0] ? acc[i][0]*INV_SCALE : MASKED_LOGIT;
            float l1 = mva[1] ? acc[i][1]*INV_SCALE : MASKED_LOGIT;
            float l2 = mva[2] ? acc[i][2]*INV_SCALE : MASKED_LOGIT;
            float l3 = mva[3] ? acc[i][3]*INV_SCALE : MASKED_LOGIT;
            *(float4*)&Lg[(size_t)(qr0 + ty*4 + i)*L_S + kbase] =
                make_float4(l0, l1, l2, l3);
            float tm = fmaxf(fmaxf(l0,l1), fmaxf(l2,l3));
            float nm = fmaxf(m[i], tm);
            s[i] = s[i]*__expf(m[i]-nm)
                 + __expf(l0-nm) + __expf(l1-nm) + __expf(l2-nm) + __expf(l3-nm);
            m[i] = nm;
        }
    }

    // reduce (m,s) across the 16 lanes sharing each row group
    #pragma unroll
    for (int i = 0; i < 4; i++) {
        #pragma unroll
        for (int off = 8; off >= 1; off >>= 1) {
            float mo = __shfl_xor_sync(0xffffffffu, m[i], off);
            float so = __shfl_xor_sync(0xffffffffu, s[i], off);
            float nm = fmaxf(m[i], mo);
            s[i] = s[i]*__expf(m[i]-nm) + so*__expf(mo-nm);
            m[i] = nm;
        }
    }
    if (tx == 0) {
        #pragma unroll
        for (int i = 0; i < 4; i++) {
            int r = qr0 + ty*4 + i;
            g_rowmax[nh*L_S + r] = m[i];
            g_rowsum[nh*L_S + r] = s[i];
        }
    }
}

// ------- kernel 3: normalize -> attn_w, and O = W @ V -------
__global__ __launch_bounds__(256) void out_head_kernel(float* __restrict__ attn_out,
                                                       int write_attn)
{
    __shared__ float Ws[BN][BM+4];              // [key][row], pad 68
    __shared__ float Vs[BN][D_H];
    __shared__ float rm[BM], ri[BM];
    int t   = threadIdx.x;
    int nh  = blockIdx.y;
    int qr0 = blockIdx.x * BM;

    const float* Lg = g_logits + (size_t)nh * L_S * L_S;
    const float* Vg = g_V      + (size_t)nh * L_S * D_H;
    float* Ag = write_attn ? (attn_out + (size_t)nh * L_S * L_S) : (float*)0;

    if (t < BM) {
        rm[t] = g_rowmax[nh*L_S + qr0 + t];
        ri[t] = 1.f / g_rowsum[nh*L_S + qr0 + t];
    }

    int tx = t & 15;                            // d pair: c0 = tx*2
    int ty = t >> 4;                            // row group: r0 = ty*4
    float acc[4][2];
    #pragma unroll
    for (int i = 0; i < 4; i++) { acc[i][0] = 0.f; acc[i][1] = 0.f; }

    for (int kt = 0; kt < L_S/BN; kt++) {
        __syncthreads();                        // covers rm/ri + prev readers
        for (int idx = t; idx < BM*BN; idx += 256) {
            int r = idx >> 6, k = idx & 63;
            size_t gidx = (size_t)(qr0 + r)*L_S + kt*BN + k;
            float w = __expf(Lg[gidx] - rm[r]) * ri[r];
            if (write_attn) Ag[gidx] = w;
            Ws[k][r] = w;
        }
        for (int idx = t; idx < BN*D_H; idx += 256) {
            int k = idx >> 5, d = idx & 31;
            Vs[k][d] = Vg[(size_t)(kt*BN + k)*D_H + d];
        }
        __syncthreads();

        #pragma unroll 8
        for (int kk = 0; kk < BN; kk++) {
            float4 w4 = *(float4*)&Ws[kk][ty*4];
            float2 v2 = *(float2*)&Vs[kk][tx*2];
            float wa[4] = {w4.x, w4.y, w4.z, w4.w};
            #pragma unroll
            for (int i = 0; i < 4; i++) {
                acc[i][0] += wa[i]*v2.x;
                acc[i][1] += wa[i]*v2.y;
            }
        }
    }

    float* Og = g_O + (size_t)nh * L_S * D_H;
    #pragma unroll
    for (int i = 0; i < 4; i++)
        *(float2*)&Og[(size_t)(qr0 + ty*4 + i)*D_H + tx*2] =
            make_float2(acc[i][0], acc[i][1]);
}

// ------- kernel 4: out = concat(O) @ Wo^T + bo -------
__global__ __launch_bounds__(256) void outproj_kernel(const float* __restrict__ Wo,
                                                      const float* __restrict__ bo,
                                                      float* __restrict__ out)
{
    __shared__ float Xs[32][EMB+1];
    __shared__ float Wsm[32][EMB+1];
    int t = threadIdx.x;
    int row0 = blockIdx.x * 32;

    for (int idx = t; idx < 32*EMB; idx += 256) {
        int r = idx >> 7, f = idx & 127;
        int row = row0 + r;
        int n = row >> 12, l = row & 4095;
        Xs[r][f] = g_O[(((size_t)n*H_N + (f>>5))*L_S + l)*D_H + (f & 31)];
    }

    int eg = t & 7;                             // 8 e-groups of 4
    int r  = t >> 3;                            // 0..31 rows
    for (int et = 0; et < 4; et++) {
        __syncthreads();
        for (int idx = t; idx < 32*EMB; idx += 256) {
            int e = idx >> 7, f = idx & 127;
            Wsm[e][f] = Wo[(size_t)(et*32 + e)*EMB + f];
        }
        __syncthreads();
        float acc[4] = {0.f, 0.f, 0.f, 0.f};
        for (int f = 0; f < EMB; f++) {
            float x = Xs[r][f];
            #pragma unroll
            for (int j = 0; j < 4; j++) acc[j] += x * Wsm[eg*4 + j][f];
        }
        #pragma unroll
        for (int j = 0; j < 4; j++) {
            int e = et*32 + eg*4 + j;
            out[(size_t)(row0 + r)*EMB + e] = acc[j] + bo[e];
        }
    }
}

// ---------------- launch ----------------
extern "C" void kernel_launch(void* const* d_in, const int* in_sizes, int n_in,
                              void* d_out, int out_size)
{
    const float* values = (const float*)d_in[0];
    const float* keys   = (const float*)d_in[1];
    const float* query  = (const float*)d_in[2];
    const int*   mask   = (const int*)d_in[3];
    const float* Wv     = (const float*)d_in[4];
    const float* Wk     = (const float*)d_in[5];
    const float* Wq     = (const float*)d_in[6];
    const float* Wo     = (const float*)d_in[7];
    const float* bo     = (const float*)d_in[8];
    float* out = (float*)d_out;

    const long long out_elems  = (long long)N_B * L_S * EMB;
    const long long attn_elems = (long long)N_B * H_N * L_S * L_S;
    int has_attn = ((long long)out_size >= out_elems + attn_elems);
    float* attn_out = has_attn ? (out + out_elems) : (float*)0;

    proj_kernel<<<(N_B*L_S*H_N)/256, 256>>>(values, keys, query, Wv, Wk, Wq);

    dim3 g1(L_S/BM, N_B*H_N);
    scores_kernel<<<g1, 256>>>(mask);
    out_head_kernel<<<g1, 256>>>(attn_out, has_attn);

    outproj_kernel<<<(N_B*L_S)/32, 256>>>(Wo, bo, out);
}

// round 5
// speedup vs baseline: 2.1783x; 2.1783x over previous
#include <cuda_runtime.h>
#include <cuda_bf16.h>
#include <math.h>
#include <stdint.h>

#define N_B 4
#define L_S 4096
#define EMB 128
#define H_N 4
#define D_H 32
/* C1 = (1/sqrt(128)) * log2(e): exp(x/sqrt(128)) = 2^(x*C1) */
#define C1 0.12751744766f
#define MASK_B2 (-1e30f)

#define TM 128
#define TK 128
#define NKT (L_S/TK)

/* smem strides (bytes) */
#define SQK 72                 /* 36 bf16 per row for Q/K tiles   */
#define SVT 272                /* 136 bf16 per row for V^T tiles  */

/* attn smem offsets */
#define O_QHI 0
#define O_QLO 9216
#define O_KHI 18432
#define O_KLO 27648
#define O_VTH 36864
#define O_VTL 45568
#define O_BIAS 54272
#define SMEM_ATTN (O_BIAS + 512)
/* stats smem offsets (reuse O_QHI..O_KLO) */
#define S_BIAS 36864
#define SMEM_STATS (S_BIAS + 512)

/* ---------------- scratch ---------------- */
__device__ float g_Q[N_B*H_N*L_S*D_H];
__device__ float g_K[N_B*H_N*L_S*D_H];
__device__ float g_V[N_B*H_N*L_S*D_H];
__device__ float g_O[N_B*H_N*L_S*D_H];
__device__ float g_nls[N_B*H_N*L_S];      /* -log2(rowsum) */

/* ---------------- helpers ---------------- */
__device__ __forceinline__ void mma_bf16(float* c, const uint32_t* a, const uint32_t* b){
    asm volatile("mma.sync.aligned.m16n8k16.row.col.f32.bf16.bf16.f32 "
        "{%0,%1,%2,%3}, {%4,%5,%6,%7}, {%8,%9}, {%0,%1,%2,%3};"
        : "+f"(c[0]), "+f"(c[1]), "+f"(c[2]), "+f"(c[3])
        : "r"(a[0]), "r"(a[1]), "r"(a[2]), "r"(a[3]), "r"(b[0]), "r"(b[1]));
}

/* branch-free exp2: valid for t <= ~120, clamps below at -126 (result ~1e-38) */
__device__ __forceinline__ float fexp2(float t){
    t = fmaxf(t, -126.0f);
    float k = t + 12582912.0f;            /* round-to-nearest-int in mantissa */
    float f = t - (k - 12582912.0f);      /* f in [-0.5, 0.5] */
    float p = 1.3333558e-3f;
    p = fmaf(p, f, 9.6181291e-3f);
    p = fmaf(p, f, 5.5504109e-2f);
    p = fmaf(p, f, 2.4022651e-1f);
    p = fmaf(p, f, 6.9314718e-1f);
    p = fmaf(p, f, 1.0f);
    float s = __int_as_float((__float_as_int(k) << 23) + 0x3F800000);
    return p * s;
}

__device__ __forceinline__ uint32_t bfbits(__nv_bfloat162 v){
    return *reinterpret_cast<uint32_t*>(&v);
}

/* load a 128x32 fp32 tile as hi/lo bf16 into [row][36bf16] smem */
__device__ __forceinline__ void load_qk_tile(char* hi, char* lo,
                                             const float* __restrict__ src, int t)
{
    for (int idx = t; idx < TM*16; idx += 256) {
        int key = idx >> 4, dp = idx & 15;
        float2 x = *(const float2*)&src[(size_t)key*D_H + dp*2];
        __nv_bfloat162 h2 = __floats2bfloat162_rn(x.x, x.y);
        float rx = x.x - __bfloat162float(h2.x);
        float ry = x.y - __bfloat162float(h2.y);
        int off = key*SQK + dp*4;
        *(uint32_t*)(hi + off) = bfbits(h2);
        *(uint32_t*)(lo + off) = bfbits(__floats2bfloat162_rn(rx, ry));
    }
}

/* load Q A-fragments for this warp (16 rows starting at wr) */
__device__ __forceinline__ void load_q_frags(const char* hi, const char* lo,
                                             int wr, int gid, int cw,
                                             uint32_t qh[2][4], uint32_t ql[2][4])
{
    #pragma unroll
    for (int ks = 0; ks < 2; ks++) {
        int b0 = (wr+gid)*SQK + ks*32 + cw;
        int b1 = (wr+gid+8)*SQK + ks*32 + cw;
        qh[ks][0] = *(const uint32_t*)(hi + b0);
        qh[ks][1] = *(const uint32_t*)(hi + b1);
        qh[ks][2] = *(const uint32_t*)(hi + b0 + 16);
        qh[ks][3] = *(const uint32_t*)(hi + b1 + 16);
        ql[ks][0] = *(const uint32_t*)(lo + b0);
        ql[ks][1] = *(const uint32_t*)(lo + b1);
        ql[ks][2] = *(const uint32_t*)(lo + b0 + 16);
        ql[ks][3] = *(const uint32_t*)(lo + b1 + 16);
    }
}

/* ---------------- kernel 1: per-head input projections ---------------- */
__global__ __launch_bounds__(256) void proj_kernel(
    const float* __restrict__ vin, const float* __restrict__ kin,
    const float* __restrict__ qin,
    const float* __restrict__ Wv, const float* __restrict__ Wk,
    const float* __restrict__ Wq)
{
    __shared__ float Ws[3][D_H*D_H];
    int t = threadIdx.x;
    for (int i = t; i < D_H*D_H; i += 256) {
        Ws[0][i] = Wq[i]; Ws[1][i] = Wk[i]; Ws[2][i] = Wv[i];
    }
    __syncthreads();

    int gid = blockIdx.x * 256 + t;
    int h  = gid & (H_N-1);
    int nl = gid >> 2;
    int n  = nl >> 12;
    int l  = nl & (L_S-1);
    size_t inbase  = (size_t)nl * EMB + h * D_H;
    size_t outbase = (((size_t)(n*H_N + h)) * L_S + l) * D_H;

    const float* ins[3]  = {qin, kin, vin};
    float*       outs[3] = {g_Q, g_K, g_V};

    for (int mm = 0; mm < 3; mm++) {
        float x[D_H];
        #pragma unroll
        for (int i = 0; i < D_H/4; i++)
            *(float4*)&x[i*4] = *(const float4*)&ins[mm][inbase + i*4];
        #pragma unroll 4
        for (int e = 0; e < D_H; e++) {
            float a = 0.f;
            #pragma unroll
            for (int d = 0; d < D_H; d++) a += x[d] * Ws[mm][e*D_H + d];
            outs[mm][outbase + e] = a;
        }
    }
}

/* ------- kernel 2: row sums (no max) via HMMA QK^T ------- */
__global__ __launch_bounds__(256) void stats_kernel(const int* __restrict__ mask)
{
    extern __shared__ char smem[];
    int t = threadIdx.x, lane = t & 31, w = t >> 5;
    int gid = lane >> 2, cw = (lane & 3) * 4, wr = w * 16;
    int nh = blockIdx.y, n = nh >> 2, qr0 = blockIdx.x * TM;
    const float* Qg = g_Q + (size_t)nh*L_S*D_H + (size_t)qr0*D_H;
    const float* Kg = g_K + (size_t)nh*L_S*D_H;
    const int* mrow = mask + n*L_S;
    float* bias2 = (float*)(smem + S_BIAS);

    load_qk_tile(smem+O_QHI, smem+O_QLO, Qg, t);
    __syncthreads();
    uint32_t qh[2][4], ql[2][4];
    load_q_frags(smem+O_QHI, smem+O_QLO, wr, gid, cw, qh, ql);

    float sum0 = 0.f, sum1 = 0.f;

    for (int kt = 0; kt < NKT; kt++) {
        __syncthreads();
        load_qk_tile(smem+O_KHI, smem+O_KLO, Kg + (size_t)kt*TK*D_H, t);
        if (t < TK) bias2[t] = mrow[kt*TK + t] ? 0.f : MASK_B2;
        __syncthreads();

        #pragma unroll 2
        for (int j = 0; j < 16; j++) {
            float c[4] = {0.f, 0.f, 0.f, 0.f};
            #pragma unroll
            for (int ks = 0; ks < 2; ks++) {
                int kb = (j*8+gid)*SQK + ks*32 + cw;
                uint32_t bh[2], bl[2];
                bh[0] = *(uint32_t*)(smem + O_KHI + kb);
                bh[1] = *(uint32_t*)(smem + O_KHI + kb + 16);
                bl[0] = *(uint32_t*)(smem + O_KLO + kb);
                bl[1] = *(uint32_t*)(smem + O_KLO + kb + 16);
                mma_bf16(c, qh[ks], bh);
                mma_bf16(c, qh[ks], bl);
                mma_bf16(c, ql[ks], bh);
            }
            float2 b2 = *(float2*)&bias2[j*8 + (cw>>1)];
            sum0 += fexp2(fmaf(c[0], C1, b2.x)) + fexp2(fmaf(c[1], C1, b2.y));
            sum1 += fexp2(fmaf(c[2], C1, b2.x)) + fexp2(fmaf(c[3], C1, b2.y));
        }
    }

    sum0 += __shfl_xor_sync(0xffffffffu, sum0, 1);
    sum0 += __shfl_xor_sync(0xffffffffu, sum0, 2);
    sum1 += __shfl_xor_sync(0xffffffffu, sum1, 1);
    sum1 += __shfl_xor_sync(0xffffffffu, sum1, 2);
    if ((lane & 3) == 0) {
        g_nls[nh*L_S + qr0 + wr + gid]     = -__log2f(sum0);
        g_nls[nh*L_S + qr0 + wr + gid + 8] = -__log2f(sum1);
    }
}

/* ------- kernel 3: recompute S, write attn_w, O = P @ V (HMMA) ------- */
__global__ __launch_bounds__(256, 2) void attn_kernel(const int* __restrict__ mask,
                                                      float* __restrict__ attn_out,
                                                      int write_attn)
{
    extern __shared__ char smem[];
    int t = threadIdx.x, lane = t & 31, w = t >> 5;
    int gid = lane >> 2, cw = (lane & 3) * 4, wr = w * 16;
    int nh = blockIdx.y, n = nh >> 2, qr0 = blockIdx.x * TM;
    const float* Qg = g_Q + (size_t)nh*L_S*D_H + (size_t)qr0*D_H;
    const float* Kg = g_K + (size_t)nh*L_S*D_H;
    const float* Vg = g_V + (size_t)nh*L_S*D_H;
    const int* mrow = mask + n*L_S;
    float* bias2 = (float*)(smem + O_BIAS);
    float* Ag = attn_out ? attn_out + (size_t)nh*L_S*L_S : (float*)0;

    float nls0 = g_nls[nh*L_S + qr0 + wr + gid];
    float nls1 = g_nls[nh*L_S + qr0 + wr + gid + 8];

    load_qk_tile(smem+O_QHI, smem+O_QLO, Qg, t);
    __syncthreads();
    uint32_t qh[2][4], ql[2][4];
    load_q_frags(smem+O_QHI, smem+O_QLO, wr, gid, cw, qh, ql);

    float o[4][4];
    #pragma unroll
    for (int jd = 0; jd < 4; jd++)
        #pragma unroll
        for (int i = 0; i < 4; i++) o[jd][i] = 0.f;

    float* Arow0 = Ag ? Ag + (size_t)(qr0 + wr + gid)*L_S : (float*)0;
    float* Arow1 = Ag ? Ag + (size_t)(qr0 + wr + gid + 8)*L_S : (float*)0;

    for (int kt = 0; kt < NKT; kt++) {
        __syncthreads();
        load_qk_tile(smem+O_KHI, smem+O_KLO, Kg + (size_t)kt*TK*D_H, t);
        /* V transposed: Vt[d][key], hi/lo */
        {
            const float* Vsrc = Vg + (size_t)kt*TK*D_H;
            for (int idx = t; idx < D_H*64; idx += 256) {
                int d = idx & 31, kp = idx >> 5;
                float x0 = Vsrc[(size_t)(kp*2)*D_H + d];
                float x1 = Vsrc[(size_t)(kp*2+1)*D_H + d];
                __nv_bfloat162 h2 = __floats2bfloat162_rn(x0, x1);
                float r0 = x0 - __bfloat162float(h2.x);
                float r1 = x1 - __bfloat162float(h2.y);
                int off = d*SVT + kp*4;
                *(uint32_t*)(smem + O_VTH + off) = bfbits(h2);
                *(uint32_t*)(smem + O_VTL + off) = bfbits(__floats2bfloat162_rn(r0, r1));
            }
        }
        if (t < TK) bias2[t] = mrow[kt*TK + t] ? 0.f : MASK_B2;
        __syncthreads();

        #pragma unroll 1
        for (int pj = 0; pj < 8; pj++) {
            int j0 = pj*2, j1 = pj*2 + 1;
            float c0[4] = {0.f,0.f,0.f,0.f};
            float c1[4] = {0.f,0.f,0.f,0.f};
            #pragma unroll
            for (int ks = 0; ks < 2; ks++) {
                uint32_t bh[2], bl[2];
                int kb0 = (j0*8+gid)*SQK + ks*32 + cw;
                bh[0] = *(uint32_t*)(smem + O_KHI + kb0);
                bh[1] = *(uint32_t*)(smem + O_KHI + kb0 + 16);
                bl[0] = *(uint32_t*)(smem + O_KLO + kb0);
                bl[1] = *(uint32_t*)(smem + O_KLO + kb0 + 16);
                mma_bf16(c0, qh[ks], bh);
                mma_bf16(c0, qh[ks], bl);
                mma_bf16(c0, ql[ks], bh);
                int kb1 = (j1*8+gid)*SQK + ks*32 + cw;
                bh[0] = *(uint32_t*)(smem + O_KHI + kb1);
                bh[1] = *(uint32_t*)(smem + O_KHI + kb1 + 16);
                bl[0] = *(uint32_t*)(smem + O_KLO + kb1);
                bl[1] = *(uint32_t*)(smem + O_KLO + kb1 + 16);
                mma_bf16(c1, qh[ks], bh);
                mma_bf16(c1, qh[ks], bl);
                mma_bf16(c1, ql[ks], bh);
            }

            float2 b2a = *(float2*)&bias2[j0*8 + (cw>>1)];
            float2 b2b = *(float2*)&bias2[j1*8 + (cw>>1)];
            float p0 = fexp2(fmaf(c0[0], C1, b2a.x + nls0));
            float p1 = fexp2(fmaf(c0[1], C1, b2a.y + nls0));
            float p2 = fexp2(fmaf(c0[2], C1, b2a.x + nls1));
            float p3 = fexp2(fmaf(c0[3], C1, b2a.y + nls1));
            float p4 = fexp2(fmaf(c1[0], C1, b2b.x + nls0));
            float p5 = fexp2(fmaf(c1[1], C1, b2b.y + nls0));
            float p6 = fexp2(fmaf(c1[2], C1, b2b.x + nls1));
            float p7 = fexp2(fmaf(c1[3], C1, b2b.y + nls1));

            if (write_attn) {
                int cb = kt*TK + (cw>>1);
                *(float2*)&Arow0[cb + j0*8] = make_float2(p0, p1);
                *(float2*)&Arow1[cb + j0*8] = make_float2(p2, p3);
                *(float2*)&Arow0[cb + j1*8] = make_float2(p4, p5);
                *(float2*)&Arow1[cb + j1*8] = make_float2(p6, p7);
            }

            /* P fragments (A-layout) for PV mma */
            uint32_t ah[4], al[4];
            __nv_bfloat162 h;
            h = __floats2bfloat162_rn(p0, p1); ah[0] = bfbits(h);
            al[0] = bfbits(__floats2bfloat162_rn(p0 - __bfloat162float(h.x),
                                                 p1 - __bfloat162float(h.y)));
            h = __floats2bfloat162_rn(p2, p3); ah[1] = bfbits(h);
            al[1] = bfbits(__floats2bfloat162_rn(p2 - __bfloat162float(h.x),
                                                 p3 - __bfloat162float(h.y)));
            h = __floats2bfloat162_rn(p4, p5); ah[2] = bfbits(h);
            al[2] = bfbits(__floats2bfloat162_rn(p4 - __bfloat162float(h.x),
                                                 p5 - __bfloat162float(h.y)));
            h = __floats2bfloat162_rn(p6, p7); ah[3] = bfbits(h);
            al[3] = bfbits(__floats2bfloat162_rn(p6 - __bfloat162float(h.x),
                                                 p7 - __bfloat162float(h.y)));

            #pragma unroll
            for (int jd = 0; jd < 4; jd++) {
                uint32_t vh[2], vl[2];
                int vb = (jd*8+gid)*SVT + pj*32 + cw;
                vh[0] = *(uint32_t*)(smem + O_VTH + vb);
                vh[1] = *(uint32_t*)(smem + O_VTH + vb + 16);
                vl[0] = *(uint32_t*)(smem + O_VTL + vb);
                vl[1] = *(uint32_t*)(smem + O_VTL + vb + 16);
                mma_bf16(o[jd], ah, vh);
                mma_bf16(o[jd], ah, vl);
                mma_bf16(o[jd], al, vh);
            }
        }
    }

    float* Og0 = g_O + (size_t)(nh*L_S + qr0 + wr + gid)*D_H;
    float* Og1 = g_O + (size_t)(nh*L_S + qr0 + wr + gid + 8)*D_H;
    #pragma unroll
    for (int jd = 0; jd < 4; jd++) {
        int col = jd*8 + (cw>>1);
        *(float2*)&Og0[col] = make_float2(o[jd][0], o[jd][1]);
        *(float2*)&Og1[col] = make_float2(o[jd][2], o[jd][3]);
    }
}

/* ------- kernel 4: out = concat(O) @ Wo^T + bo ------- */
__global__ __launch_bounds__(256) void outproj_kernel(const float* __restrict__ Wo,
                                                      const float* __restrict__ bo,
                                                      float* __restrict__ out)
{
    __shared__ float Xs[32][EMB+1];
    __shared__ float Wsm[32][EMB+1];
    int t = threadIdx.x;
    int row0 = blockIdx.x * 32;

    for (int idx = t; idx < 32*EMB; idx += 256) {
        int r = idx >> 7, f = idx & 127;
        int row = row0 + r;
        int n = row >> 12, l = row & 4095;
        Xs[r][f] = g_O[(((size_t)n*H_N + (f>>5))*L_S + l)*D_H + (f & 31)];
    }

    int eg = t & 7;
    int r  = t >> 3;
    for (int et = 0; et < 4; et++) {
        __syncthreads();
        for (int idx = t; idx < 32*EMB; idx += 256) {
            int e = idx >> 7, f = idx & 127;
            Wsm[e][f] = Wo[(size_t)(et*32 + e)*EMB + f];
        }
        __syncthreads();
        float acc[4] = {0.f, 0.f, 0.f, 0.f};
        for (int f = 0; f < EMB; f++) {
            float x = Xs[r][f];
            #pragma unroll
            for (int j = 0; j < 4; j++) acc[j] += x * Wsm[eg*4 + j][f];
        }
        #pragma unroll
        for (int j = 0; j < 4; j++) {
            int e = et*32 + eg*4 + j;
            out[(size_t)(row0 + r)*EMB + e] = acc[j] + bo[e];
        }
    }
}

/* ---------------- launch ---------------- */
extern "C" void kernel_launch(void* const* d_in, const int* in_sizes, int n_in,
                              void* d_out, int out_size)
{
    const float* values = (const float*)d_in[0];
    const float* keys   = (const float*)d_in[1];
    const float* query  = (const float*)d_in[2];
    const int*   mask   = (const int*)d_in[3];
    const float* Wv     = (const float*)d_in[4];
    const float* Wk     = (const float*)d_in[5];
    const float* Wq     = (const float*)d_in[6];
    const float* Wo     = (const float*)d_in[7];
    const float* bo     = (const float*)d_in[8];
    float* out = (float*)d_out;

    const long long out_elems  = (long long)N_B * L_S * EMB;
    const long long attn_elems = (long long)N_B * H_N * L_S * L_S;
    int has_attn = ((long long)out_size >= out_elems + attn_elems);
    float* attn_out = has_attn ? (out + out_elems) : (float*)0;

    cudaFuncSetAttribute(stats_kernel, cudaFuncAttributeMaxDynamicSharedMemorySize, SMEM_STATS);
    cudaFuncSetAttribute(attn_kernel,  cudaFuncAttributeMaxDynamicSharedMemorySize, SMEM_ATTN);

    proj_kernel<<<(N_B*L_S*H_N)/256, 256>>>(values, keys, query, Wv, Wk, Wq);

    dim3 g(L_S/TM, N_B*H_N);
    stats_kernel<<<g, 256, SMEM_STATS>>>(mask);
    attn_kernel<<<g, 256, SMEM_ATTN>>>(mask, attn_out, has_attn);

    outproj_kernel<<<(N_B*L_S)/32, 256>>>(Wo, bo, out);
}

// round 6
// speedup vs baseline: 2.8974x; 1.3301x over previous
#include <cuda_runtime.h>
#include <cuda_fp16.h>
#include <math.h>
#include <stdint.h>

#define N_B 4
#define L_S 4096
#define EMB 128
#define H_N 4
#define D_H 32
/* C1 = (1/sqrt(128)) * log2(e) */
#define C1 0.12751744766f
#define MASK_B2 (-1e30f)

#define TM 128
#define TK 128
#define NKT (L_S/TK)

/* plane strides (bytes): chosen so tile-convert writes and ldmatrix reads are bank-conflict-free */
#define PSQ 2080           /* QK tiles: 4 d-half planes of [128 rows][16B] */
#define PSV 576            /* V^T: 16 key-octet planes of [32 d][16B]      */

/* attn smem offsets */
#define A_QHI 0
#define A_QLO (A_QHI + 4*PSQ)
#define A_KHI (A_QLO + 4*PSQ)
#define A_KLO (A_KHI + 4*PSQ)
#define A_VTH (A_KLO + 4*PSQ)
#define A_BIAS (A_VTH + 16*PSV)
#define SMEM_ATTN (A_BIAS + 512)
/* stats smem offsets */
#define S_QHI 0
#define S_KHI (S_QHI + 4*PSQ)
#define S_BIAS (S_KHI + 4*PSQ)
#define SMEM_STATS (S_BIAS + 512)

/* ---------------- scratch ---------------- */
__device__ float g_Q[N_B*H_N*L_S*D_H];
__device__ float g_K[N_B*H_N*L_S*D_H];
__device__ float g_V[N_B*H_N*L_S*D_H];
__device__ float g_O[N_B*H_N*L_S*D_H];
__device__ float g_nls[N_B*H_N*L_S];      /* -log2(rowsum) */

/* ---------------- helpers ---------------- */
__device__ __forceinline__ uint32_t smem_u32(const void* p){
    uint32_t a;
    asm("{ .reg .u64 t; cvta.to.shared.u64 t, %1; cvt.u32.u64 %0, t; }" : "=r"(a) : "l"(p));
    return a;
}

__device__ __forceinline__ void mma_f16(float* c, const uint32_t* a, const uint32_t* b){
    asm volatile("mma.sync.aligned.m16n8k16.row.col.f32.f16.f16.f32 "
        "{%0,%1,%2,%3}, {%4,%5,%6,%7}, {%8,%9}, {%0,%1,%2,%3};"
        : "+f"(c[0]), "+f"(c[1]), "+f"(c[2]), "+f"(c[3])
        : "r"(a[0]), "r"(a[1]), "r"(a[2]), "r"(a[3]), "r"(b[0]), "r"(b[1]));
}

#define LDMX4(r, a) \
    asm volatile("ldmatrix.sync.aligned.m8n8.x4.shared.b16 {%0,%1,%2,%3}, [%4];" \
        : "=r"((r)[0]), "=r"((r)[1]), "=r"((r)[2]), "=r"((r)[3]) : "r"(a))

/* branch-free exp2 */
__device__ __forceinline__ float fexp2(float t){
    t = fmaxf(t, -126.0f);
    float k = t + 12582912.0f;
    float f = t - (k - 12582912.0f);
    float p = 1.3333558e-3f;
    p = fmaf(p, f, 9.6181291e-3f);
    p = fmaf(p, f, 5.5504109e-2f);
    p = fmaf(p, f, 2.4022651e-1f);
    p = fmaf(p, f, 6.9314718e-1f);
    p = fmaf(p, f, 1.0f);
    float s = __int_as_float((__float_as_int(k) << 23) + 0x3F800000);
    return p * s;
}

__device__ __forceinline__ uint32_t h2bits(__half2 v){
    return *reinterpret_cast<uint32_t*>(&v);
}

/* convert 128x32 fp32 tile -> fp16 hi(/lo) planes. plane = d-half, row-major 16B rows */
__device__ __forceinline__ void conv_qk_hilo(char* hi, char* lo,
                                             const float* __restrict__ src, int t)
{
    #pragma unroll
    for (int it = 0; it < 8; it++) {
        int idx = it*256 + t;
        int row = idx >> 4, dp = idx & 15;
        float2 x = *(const float2*)&src[(size_t)row*D_H + dp*2];
        __half2 h2 = __floats2half2_rn(x.x, x.y);
        float rx = x.x - __half2float(__low2half(h2));
        float ry = x.y - __half2float(__high2half(h2));
        int off = (dp>>2)*PSQ + row*16 + (dp&3)*4;
        *(uint32_t*)(hi + off) = h2bits(h2);
        *(uint32_t*)(lo + off) = h2bits(__floats2half2_rn(rx, ry));
    }
}
__device__ __forceinline__ void conv_qk_hi(char* hi, const float* __restrict__ src, int t)
{
    #pragma unroll
    for (int it = 0; it < 8; it++) {
        int idx = it*256 + t;
        int row = idx >> 4, dp = idx & 15;
        float2 x = *(const float2*)&src[(size_t)row*D_H + dp*2];
        int off = (dp>>2)*PSQ + row*16 + (dp&3)*4;
        *(uint32_t*)(hi + off) = h2bits(__floats2half2_rn(x.x, x.y));
    }
}

/* Q A-fragments via ldmatrix: qf[ks][0..3] for rows wr..wr+15 */
__device__ __forceinline__ void q_frags(uint32_t sbase, int off, int wr, int lane,
                                        uint32_t qf[2][4])
{
    int m = lane >> 3;
    int row = wr + (m & 1)*8 + (lane & 7);
    uint32_t a0 = sbase + off + (m >> 1)*PSQ + row*16;        /* planes 0,1 */
    LDMX4(qf[0], a0);
    LDMX4(qf[1], a0 + 2*PSQ);                                  /* planes 2,3 */
}

/* ---------------- kernel 1: per-head input projections ---------------- */
__global__ __launch_bounds__(256) void proj_kernel(
    const float* __restrict__ vin, const float* __restrict__ kin,
    const float* __restrict__ qin,
    const float* __restrict__ Wv, const float* __restrict__ Wk,
    const float* __restrict__ Wq)
{
    __shared__ float Ws[3][D_H*D_H];
    int t = threadIdx.x;
    for (int i = t; i < D_H*D_H; i += 256) {
        Ws[0][i] = Wq[i]; Ws[1][i] = Wk[i]; Ws[2][i] = Wv[i];
    }
    __syncthreads();

    int gid = blockIdx.x * 256 + t;
    int h  = gid & (H_N-1);
    int nl = gid >> 2;
    int n  = nl >> 12;
    int l  = nl & (L_S-1);
    size_t inbase  = (size_t)nl * EMB + h * D_H;
    size_t outbase = (((size_t)(n*H_N + h)) * L_S + l) * D_H;

    const float* ins[3]  = {qin, kin, vin};
    float*       outs[3] = {g_Q, g_K, g_V};

    for (int mm = 0; mm < 3; mm++) {
        float x[D_H];
        #pragma unroll
        for (int i = 0; i < D_H/4; i++)
            *(float4*)&x[i*4] = *(const float4*)&ins[mm][inbase + i*4];
        #pragma unroll 4
        for (int e = 0; e < D_H; e++) {
            float a = 0.f;
            #pragma unroll
            for (int d = 0; d < D_H; d++) a += x[d] * Ws[mm][e*D_H + d];
            outs[mm][outbase + e] = a;
        }
    }
}

/* ------- kernel 2: row sums via fp16 1-split HMMA QK^T ------- */
__global__ __launch_bounds__(256, 3) void stats_kernel(const int* __restrict__ mask)
{
    extern __shared__ char smem[];
    uint32_t sb = smem_u32(smem);
    int t = threadIdx.x, lane = t & 31, w = t >> 5;
    int gid = lane >> 2, cp = (lane & 3)*2, wr = w*16;
    int nh = blockIdx.y, n = nh >> 2, qr0 = blockIdx.x * TM;
    const float* Qg = g_Q + (size_t)nh*L_S*D_H + (size_t)qr0*D_H;
    const float* Kg = g_K + (size_t)nh*L_S*D_H;
    const int* mrow = mask + n*L_S;
    float* bias = (float*)(smem + S_BIAS);

    conv_qk_hi(smem + S_QHI, Qg, t);
    __syncthreads();
    uint32_t qh[2][4];
    q_frags(sb, S_QHI, wr, lane, qh);

    /* K ldmatrix base: matrix m = plane (d-half), row = j*8 + lane&7 */
    uint32_t kb = sb + S_KHI + (lane>>3)*PSQ + (lane&7)*16;

    float sum0 = 0.f, sum1 = 0.f;

    for (int kt = 0; kt < NKT; kt++) {
        __syncthreads();
        conv_qk_hi(smem + S_KHI, Kg + (size_t)kt*TK*D_H, t);
        if (t < TK) bias[t] = mrow[kt*TK + t] ? 0.f : MASK_B2;
        __syncthreads();

        #pragma unroll 2
        for (int pj = 0; pj < 8; pj++) {
            uint32_t k0[4], k1[4];
            LDMX4(k0, kb + (pj*2)*128);
            LDMX4(k1, kb + (pj*2+1)*128);
            float c0[4] = {0.f,0.f,0.f,0.f};
            float c1[4] = {0.f,0.f,0.f,0.f};
            mma_f16(c0, qh[0], k0);
            mma_f16(c1, qh[0], k1);
            mma_f16(c0, qh[1], k0 + 2);
            mma_f16(c1, qh[1], k1 + 2);

            float2 ba = *(float2*)&bias[pj*16 + cp];
            float2 bb = *(float2*)&bias[pj*16 + 8 + cp];
            sum0 += fexp2(fmaf(c0[0], C1, ba.x)) + fexp2(fmaf(c0[1], C1, ba.y))
                  + fexp2(fmaf(c1[0], C1, bb.x)) + fexp2(fmaf(c1[1], C1, bb.y));
            sum1 += fexp2(fmaf(c0[2], C1, ba.x)) + fexp2(fmaf(c0[3], C1, ba.y))
                  + fexp2(fmaf(c1[2], C1, bb.x)) + fexp2(fmaf(c1[3], C1, bb.y));
        }
    }

    sum0 += __shfl_xor_sync(0xffffffffu, sum0, 1);
    sum0 += __shfl_xor_sync(0xffffffffu, sum0, 2);
    sum1 += __shfl_xor_sync(0xffffffffu, sum1, 1);
    sum1 += __shfl_xor_sync(0xffffffffu, sum1, 2);
    if ((lane & 3) == 0) {
        g_nls[nh*L_S + qr0 + wr + gid]     = -__log2f(sum0);
        g_nls[nh*L_S + qr0 + wr + gid + 8] = -__log2f(sum1);
    }
}

/* ------- kernel 3: recompute S (fp16 3-split), write attn_w, O = P @ V ------- */
__global__ __launch_bounds__(256, 2) void attn_kernel(const int* __restrict__ mask,
                                                      float* __restrict__ attn_out,
                                                      int write_attn)
{
    extern __shared__ char smem[];
    uint32_t sb = smem_u32(smem);
    int t = threadIdx.x, lane = t & 31, w = t >> 5;
    int gid = lane >> 2, cp = (lane & 3)*2, wr = w*16;
    int nh = blockIdx.y, n = nh >> 2, qr0 = blockIdx.x * TM;
    const float* Qg = g_Q + (size_t)nh*L_S*D_H + (size_t)qr0*D_H;
    const float* Kg = g_K + (size_t)nh*L_S*D_H;
    const float* Vg = g_V + (size_t)nh*L_S*D_H;
    const int* mrow = mask + n*L_S;
    float* bias = (float*)(smem + A_BIAS);
    float* Ag = attn_out ? attn_out + (size_t)nh*L_S*L_S : (float*)0;

    float nls0 = g_nls[nh*L_S + qr0 + wr + gid];
    float nls1 = g_nls[nh*L_S + qr0 + wr + gid + 8];

    conv_qk_hilo(smem + A_QHI, smem + A_QLO, Qg, t);
    __syncthreads();
    uint32_t qh[2][4], ql[2][4];
    q_frags(sb, A_QHI, wr, lane, qh);
    q_frags(sb, A_QLO, wr, lane, ql);

    /* ldmatrix bases */
    uint32_t kbh = sb + A_KHI + (lane>>3)*PSQ + (lane&7)*16;
    uint32_t kbl = sb + A_KLO + (lane>>3)*PSQ + (lane&7)*16;
    /* V: x4 matrices: m = lane>>3 -> jd = m>>1, octet = m&1; row d = jd*8 + lane&7 */
    uint32_t vb = sb + A_VTH + ((lane>>3)&1)*PSV + (((lane>>3)>>1)*8 + (lane&7))*16;

    float o[4][4];
    #pragma unroll
    for (int jd = 0; jd < 4; jd++)
        #pragma unroll
        for (int i = 0; i < 4; i++) o[jd][i] = 0.f;

    float* Arow0 = Ag ? Ag + (size_t)(qr0 + wr + gid)*L_S : (float*)0;
    float* Arow1 = Ag ? Ag + (size_t)(qr0 + wr + gid + 8)*L_S : (float*)0;

    for (int kt = 0; kt < NKT; kt++) {
        __syncthreads();
        conv_qk_hilo(smem + A_KHI, smem + A_KLO, Kg + (size_t)kt*TK*D_H, t);
        /* V^T fp16 hi: plane = key-octet, row = d, 16B = 8 keys */
        {
            const float* Vsrc = Vg + (size_t)kt*TK*D_H;
            #pragma unroll
            for (int it = 0; it < 8; it++) {
                int kp = (t & 7) + it*8;
                int d  = (t >> 3) & 31;
                float x0 = Vsrc[(size_t)(kp*2)*D_H + d];
                float x1 = Vsrc[(size_t)(kp*2+1)*D_H + d];
                int off = A_VTH + (kp>>2)*PSV + d*16 + (kp&3)*4;
                *(uint32_t*)(smem + off) = h2bits(__floats2half2_rn(x0, x1));
            }
        }
        if (t < TK) bias[t] = mrow[kt*TK + t] ? 0.f : MASK_B2;
        __syncthreads();

        #pragma unroll 1
        for (int pj = 0; pj < 8; pj++) {
            uint32_t kh0[4], kh1[4], kl0[4], kl1[4];
            LDMX4(kh0, kbh + (pj*2)*128);
            LDMX4(kh1, kbh + (pj*2+1)*128);
            LDMX4(kl0, kbl + (pj*2)*128);
            LDMX4(kl1, kbl + (pj*2+1)*128);

            float c0[4] = {0.f,0.f,0.f,0.f};
            float c1[4] = {0.f,0.f,0.f,0.f};
            #pragma unroll
            for (int ks = 0; ks < 2; ks++) {
                mma_f16(c0, qh[ks], kh0 + ks*2);
                mma_f16(c1, qh[ks], kh1 + ks*2);
                mma_f16(c0, qh[ks], kl0 + ks*2);
                mma_f16(c1, qh[ks], kl1 + ks*2);
                mma_f16(c0, ql[ks], kh0 + ks*2);
                mma_f16(c1, ql[ks], kh1 + ks*2);
            }

            float2 ba = *(float2*)&bias[pj*16 + cp];
            float2 bb = *(float2*)&bias[pj*16 + 8 + cp];
            float p0 = fexp2(fmaf(c0[0], C1, ba.x + nls0));
            float p1 = fexp2(fmaf(c0[1], C1, ba.y + nls0));
            float p2 = fexp2(fmaf(c0[2], C1, ba.x + nls1));
            float p3 = fexp2(fmaf(c0[3], C1, ba.y + nls1));
            float p4 = fexp2(fmaf(c1[0], C1, bb.x + nls0));
            float p5 = fexp2(fmaf(c1[1], C1, bb.y + nls0));
            float p6 = fexp2(fmaf(c1[2], C1, bb.x + nls1));
            float p7 = fexp2(fmaf(c1[3], C1, bb.y + nls1));

            if (write_attn) {
                int cb = kt*TK + pj*16 + cp;
                *(float2*)&Arow0[cb]     = make_float2(p0, p1);
                *(float2*)&Arow1[cb]     = make_float2(p2, p3);
                *(float2*)&Arow0[cb + 8] = make_float2(p4, p5);
                *(float2*)&Arow1[cb + 8] = make_float2(p6, p7);
            }

            /* P = ph + pl (exact split), V fp16-rounded */
            uint32_t ah[4], al[4];
            __half2 h;
            h = __floats2half2_rn(p0, p1); ah[0] = h2bits(h);
            al[0] = h2bits(__floats2half2_rn(p0 - __half2float(__low2half(h)),
                                             p1 - __half2float(__high2half(h))));
            h = __floats2half2_rn(p2, p3); ah[1] = h2bits(h);
            al[1] = h2bits(__floats2half2_rn(p2 - __half2float(__low2half(h)),
                                             p3 - __half2float(__high2half(h))));
            h = __floats2half2_rn(p4, p5); ah[2] = h2bits(h);
            al[2] = h2bits(__floats2half2_rn(p4 - __half2float(__low2half(h)),
                                             p5 - __half2float(__high2half(h))));
            h = __floats2half2_rn(p6, p7); ah[3] = h2bits(h);
            al[3] = h2bits(__floats2half2_rn(p6 - __half2float(__low2half(h)),
                                             p7 - __half2float(__high2half(h))));

            uint32_t va[4], vb2[4];
            LDMX4(va,  vb + (2*pj)*PSV);          /* jd 0,1: (o0,o1) each */
            LDMX4(vb2, vb + (2*pj)*PSV + 16*16);  /* jd 2,3 (d += 16) */

            mma_f16(o[0], ah, va);
            mma_f16(o[1], ah, va + 2);
            mma_f16(o[2], ah, vb2);
            mma_f16(o[3], ah, vb2 + 2);
            mma_f16(o[0], al, va);
            mma_f16(o[1], al, va + 2);
            mma_f16(o[2], al, vb2);
            mma_f16(o[3], al, vb2 + 2);
        }
    }

    float* Og0 = g_O + (size_t)(nh*L_S + qr0 + wr + gid)*D_H;
    float* Og1 = g_O + (size_t)(nh*L_S + qr0 + wr + gid + 8)*D_H;
    #pragma unroll
    for (int jd = 0; jd < 4; jd++) {
        int col = jd*8 + cp;
        *(float2*)&Og0[col] = make_float2(o[jd][0], o[jd][1]);
        *(float2*)&Og1[col] = make_float2(o[jd][2], o[jd][3]);
    }
}

/* ------- kernel 4: out = concat(O) @ Wo^T + bo ------- */
__global__ __launch_bounds__(256) void outproj_kernel(const float* __restrict__ Wo,
                                                      const float* __restrict__ bo,
                                                      float* __restrict__ out)
{
    __shared__ float Xs[32][EMB+1];
    __shared__ float Wsm[32][EMB+1];
    int t = threadIdx.x;
    int row0 = blockIdx.x * 32;

    for (int idx = t; idx < 32*EMB; idx += 256) {
        int r = idx >> 7, f = idx & 127;
        int row = row0 + r;
        int n = row >> 12, l = row & 4095;
        Xs[r][f] = g_O[(((size_t)n*H_N + (f>>5))*L_S + l)*D_H + (f & 31)];
    }

    int eg = t & 7;
    int r  = t >> 3;
    for (int et = 0; et < 4; et++) {
        __syncthreads();
        for (int idx = t; idx < 32*EMB; idx += 256) {
            int e = idx >> 7, f = idx & 127;
            Wsm[e][f] = Wo[(size_t)(et*32 + e)*EMB + f];
        }
        __syncthreads();
        float acc[4] = {0.f, 0.f, 0.f, 0.f};
        for (int f = 0; f < EMB; f++) {
            float x = Xs[r][f];
            #pragma unroll
            for (int j = 0; j < 4; j++) acc[j] += x * Wsm[eg*4 + j][f];
        }
        #pragma unroll
        for (int j = 0; j < 4; j++) {
            int e = et*32 + eg*4 + j;
            out[(size_t)(row0 + r)*EMB + e] = acc[j] + bo[e];
        }
    }
}

/* ---------------- launch ---------------- */
extern "C" void kernel_launch(void* const* d_in, const int* in_sizes, int n_in,
                              void* d_out, int out_size)
{
    const float* values = (const float*)d_in[0];
    const float* keys   = (const float*)d_in[1];
    const float* query  = (const float*)d_in[2];
    const int*   mask   = (const int*)d_in[3];
    const float* Wv     = (const float*)d_in[4];
    const float* Wk     = (const float*)d_in[5];
    const float* Wq     = (const float*)d_in[6];
    const float* Wo     = (const float*)d_in[7];
    const float* bo     = (const float*)d_in[8];
    float* out = (float*)d_out;

    const long long out_elems  = (long long)N_B * L_S * EMB;
    const long long attn_elems = (long long)N_B * H_N * L_S * L_S;
    int has_attn = ((long long)out_size >= out_elems + attn_elems);
    float* attn_out = has_attn ? (out + out_elems) : (float*)0;

    cudaFuncSetAttribute(stats_kernel, cudaFuncAttributeMaxDynamicSharedMemorySize, SMEM_STATS);
    cudaFuncSetAttribute(attn_kernel,  cudaFuncAttributeMaxDynamicSharedMemorySize, SMEM_ATTN);

    proj_kernel<<<(N_B*L_S*H_N)/256, 256>>>(values, keys, query, Wv, Wk, Wq);

    dim3 g(L_S/TM, N_B*H_N);
    stats_kernel<<<g, 256, SMEM_STATS>>>(mask);
    attn_kernel<<<g, 256, SMEM_ATTN>>>(mask, attn_out, has_attn);

    outproj_kernel<<<(N_B*L_S)/32, 256>>>(Wo, bo, out);
}

// round 7
// speedup vs baseline: 3.2378x; 1.1175x over previous
#include <cuda_runtime.h>
#include <cuda_fp16.h>
#include <math.h>
#include <stdint.h>

#define N_B 4
#define L_S 4096
#define EMB 128
#define H_N 4
#define D_H 32
#define C1 0.12751744766f       /* (1/sqrt(128)) * log2(e) */
#define MASK_B2 (-1e30f)

#define TM 128
#define TK 128
#define NKT (L_S/TK)
#define NH (N_B*H_N)

/* packed plane strides (bytes) */
#define PSQ 2048               /* QK image: 4 d-octet planes of [128 rows][16B] */
#define PSV 512                /* V image: 16 key-octet planes of [32 d][16B]   */
#define TILE_U4 512            /* 8192 bytes per tile image = 512 uint4 */

/* attn smem offsets */
#define A_QHI 0
#define A_QLO 8192
#define A_STG 16384
#define A_STGSZ 24576          /* Kh(8K) + Kl(8K) + Vt(8K) */
#define A_BIAS 65536
#define SMEM_ATTN (A_BIAS + 16384)
/* stats smem offsets */
#define S_QHI 0
#define S_STG 8192
#define S_BIAS 24576
#define SMEM_STATS (S_BIAS + 16384)

/* ---------------- scratch ---------------- */
__device__ float g_Q[NH*L_S*D_H];
__device__ float g_K[NH*L_S*D_H];
__device__ float g_V[NH*L_S*D_H];
__device__ float g_O[NH*L_S*D_H];
__device__ float g_nls[NH*L_S];
__device__ uint4 g_imgQh[NH*NKT*TILE_U4];
__device__ uint4 g_imgQl[NH*NKT*TILE_U4];
__device__ uint4 g_imgKh[NH*NKT*TILE_U4];
__device__ uint4 g_imgKl[NH*NKT*TILE_U4];
__device__ uint4 g_imgVt[NH*NKT*TILE_U4];

/* ---------------- helpers ---------------- */
__device__ __forceinline__ uint32_t smem_u32(const void* p){
    uint32_t a;
    asm("{ .reg .u64 t; cvta.to.shared.u64 t, %1; cvt.u32.u64 %0, t; }" : "=r"(a) : "l"(p));
    return a;
}
__device__ __forceinline__ void mma_f16(float* c, const uint32_t* a, const uint32_t* b){
    asm volatile("mma.sync.aligned.m16n8k16.row.col.f32.f16.f16.f32 "
        "{%0,%1,%2,%3}, {%4,%5,%6,%7}, {%8,%9}, {%0,%1,%2,%3};"
        : "+f"(c[0]), "+f"(c[1]), "+f"(c[2]), "+f"(c[3])
        : "r"(a[0]), "r"(a[1]), "r"(a[2]), "r"(a[3]), "r"(b[0]), "r"(b[1]));
}
#define LDMX4(r, a) \
    asm volatile("ldmatrix.sync.aligned.m8n8.x4.shared.b16 {%0,%1,%2,%3}, [%4];" \
        : "=r"((r)[0]), "=r"((r)[1]), "=r"((r)[2]), "=r"((r)[3]) : "r"(a))
#define CPA16(dst, src) \
    asm volatile("cp.async.cg.shared.global [%0], [%1], 16;" :: "r"(dst), "l"(src))
#define CPA_COMMIT() asm volatile("cp.async.commit_group;" ::: "memory")
#define CPA_WAIT(n)  asm volatile("cp.async.wait_group %0;" :: "n"(n) : "memory")

__device__ __forceinline__ float fexp2(float t){
    t = fmaxf(t, -126.0f);
    float k = t + 12582912.0f;
    float f = t - (k - 12582912.0f);
    float p = 1.3333558e-3f;
    p = fmaf(p, f, 9.6181291e-3f);
    p = fmaf(p, f, 5.5504109e-2f);
    p = fmaf(p, f, 2.4022651e-1f);
    p = fmaf(p, f, 6.9314718e-1f);
    p = fmaf(p, f, 1.0f);
    float s = __int_as_float((__float_as_int(k) << 23) + 0x3F800000);
    return p * s;
}
__device__ __forceinline__ uint32_t h2bits(__half2 v){
    return *reinterpret_cast<uint32_t*>(&v);
}

/* Q A-fragments via ldmatrix from plane image in smem */
__device__ __forceinline__ void q_frags(uint32_t base, int wr, int lane, uint32_t qf[2][4])
{
    int m = lane >> 3;
    int row = wr + (m & 1)*8 + (lane & 7);
    uint32_t a0 = base + (m >> 1)*PSQ + row*16;
    LDMX4(qf[0], a0);
    LDMX4(qf[1], a0 + 2*PSQ);
}

/* ---------------- kernel 1: per-head input projections ---------------- */
__global__ __launch_bounds__(256) void proj_kernel(
    const float* __restrict__ vin, const float* __restrict__ kin,
    const float* __restrict__ qin,
    const float* __restrict__ Wv, const float* __restrict__ Wk,
    const float* __restrict__ Wq)
{
    __shared__ float Ws[3][D_H*D_H];
    int t = threadIdx.x;
    for (int i = t; i < D_H*D_H; i += 256) {
        Ws[0][i] = Wq[i]; Ws[1][i] = Wk[i]; Ws[2][i] = Wv[i];
    }
    __syncthreads();

    int gid = blockIdx.x * 256 + t;
    int h  = gid & (H_N-1);
    int nl = gid >> 2;
    int n  = nl >> 12;
    int l  = nl & (L_S-1);
    size_t inbase  = (size_t)nl * EMB + h * D_H;
    size_t outbase = (((size_t)(n*H_N + h)) * L_S + l) * D_H;

    const float* ins[3]  = {qin, kin, vin};
    float*       outs[3] = {g_Q, g_K, g_V};

    for (int mm = 0; mm < 3; mm++) {
        float x[D_H];
        #pragma unroll
        for (int i = 0; i < D_H/4; i++)
            *(float4*)&x[i*4] = *(const float4*)&ins[mm][inbase + i*4];
        #pragma unroll 4
        for (int e = 0; e < D_H; e++) {
            float a = 0.f;
            #pragma unroll
            for (int d = 0; d < D_H; d++) a += x[d] * Ws[mm][e*D_H + d];
            outs[mm][outbase + e] = a;
        }
    }
}

/* ------- kernel 1b: build fp16 tile images ------- */
__global__ __launch_bounds__(256) void conv_kernel()
{
    __shared__ float tile[128*33];
    int t = threadIdx.x;
    int kt = blockIdx.x, nh = blockIdx.y;
    size_t src = ((size_t)nh*L_S + (size_t)kt*128) * D_H;
    size_t ti = (size_t)(nh*NKT + kt) * TILE_U4;

    /* --- Q and K: hi/lo plane images --- */
    const float* srcs[2] = { g_Q + src, g_K + src };
    uint4* hidst[2] = { g_imgQh + ti, g_imgKh + ti };
    uint4* lodst[2] = { g_imgQl + ti, g_imgKl + ti };
    for (int mm = 0; mm < 2; mm++) {
        __syncthreads();
        for (int idx = t; idx < 1024; idx += 256) {
            int r = idx >> 3, c4 = idx & 7;
            float4 x = *(const float4*)&srcs[mm][(size_t)r*32 + c4*4];
            float* drow = &tile[r*33 + c4*4];
            drow[0] = x.x; drow[1] = x.y; drow[2] = x.z; drow[3] = x.w;
        }
        __syncthreads();
        #pragma unroll
        for (int i = 0; i < 2; i++) {
            int item = t + i*256;
            int p = item >> 7, r = item & 127;
            const float* row = &tile[r*33 + p*8];
            uint32_t hw[4], lw[4];
            #pragma unroll
            for (int w2 = 0; w2 < 4; w2++) {
                float x0 = row[w2*2], x1 = row[w2*2+1];
                __half2 h = __floats2half2_rn(x0, x1);
                hw[w2] = h2bits(h);
                lw[w2] = h2bits(__floats2half2_rn(x0 - __half2float(__low2half(h)),
                                                  x1 - __half2float(__high2half(h))));
            }
            hidst[mm][item] = make_uint4(hw[0], hw[1], hw[2], hw[3]);
            lodst[mm][item] = make_uint4(lw[0], lw[1], lw[2], lw[3]);
        }
    }

    /* --- V: transposed octet image (hi only) --- */
    __syncthreads();
    for (int idx = t; idx < 1024; idx += 256) {
        int r = idx >> 3, c4 = idx & 7;
        float4 x = *(const float4*)&g_V[src + (size_t)r*32 + c4*4];
        float* drow = &tile[r*33 + c4*4];
        drow[0] = x.x; drow[1] = x.y; drow[2] = x.z; drow[3] = x.w;
    }
    __syncthreads();
    #pragma unroll
    for (int i = 0; i < 2; i++) {
        int item = t + i*256;
        int oct = item >> 5, d = item & 31;
        uint32_t w[4];
        #pragma unroll
        for (int w2 = 0; w2 < 4; w2++) {
            float x0 = tile[(oct*8 + w2*2)*33 + d];
            float x1 = tile[(oct*8 + w2*2 + 1)*33 + d];
            w[w2] = h2bits(__floats2half2_rn(x0, x1));
        }
        g_imgVt[ti + item] = make_uint4(w[0], w[1], w[2], w[3]);
    }
}

/* ------- kernel 2: row sums via fp16 1-split HMMA QK^T ------- */
__global__ __launch_bounds__(256, 3) void stats_kernel(const int* __restrict__ mask)
{
    extern __shared__ char smem[];
    uint32_t sb = smem_u32(smem);
    int t = threadIdx.x, lane = t & 31, w = t >> 5;
    int gid = lane >> 2, cp = (lane & 3)*2, wr = w*16;
    int nh = blockIdx.y, n = nh >> 2, qt = blockIdx.x, qr0 = qt * TM;
    const int* mrow = mask + n*L_S;
    float* bias = (float*)(smem + S_BIAS);

    const uint4* Qh = g_imgQh + (size_t)(nh*NKT + qt)*TILE_U4;
    const uint4* Kh = g_imgKh + (size_t)nh*NKT*TILE_U4;

    /* prologue: Q + stage0 */
    #pragma unroll
    for (int i = 0; i < 2; i++) {
        CPA16(sb + S_QHI + (t + i*256)*16, Qh + t + i*256);
        CPA16(sb + S_STG + (t + i*256)*16, Kh + t + i*256);
    }
    CPA_COMMIT();
    #pragma unroll
    for (int i = 0; i < 16; i++) {
        int idx = t + i*256;
        bias[idx] = mrow[idx] ? 0.f : MASK_B2;
    }
    CPA_WAIT(0);
    __syncthreads();

    uint32_t qh[2][4];
    q_frags(sb + S_QHI, wr, lane, qh);

    float sum0 = 0.f, sum1 = 0.f;

    for (int kt = 0; kt < NKT; kt++) {
        if (kt + 1 < NKT) {
            uint32_t st = sb + S_STG + ((kt+1)&1)*8192;
            const uint4* src = Kh + (size_t)(kt+1)*TILE_U4;
            CPA16(st + t*16, src + t);
            CPA16(st + (t+256)*16, src + t + 256);
        }
        CPA_COMMIT();
        CPA_WAIT(1);
        __syncthreads();

        uint32_t kb = sb + S_STG + (kt&1)*8192 + (lane>>3)*PSQ + (lane&7)*16;
        const float* brow = bias + kt*TK;

        #pragma unroll 2
        for (int pj = 0; pj < 8; pj++) {
            uint32_t k0[4], k1[4];
            LDMX4(k0, kb + (pj*2)*128);
            LDMX4(k1, kb + (pj*2+1)*128);
            float c0[4] = {0.f,0.f,0.f,0.f};
            float c1[4] = {0.f,0.f,0.f,0.f};
            mma_f16(c0, qh[0], k0);
            mma_f16(c1, qh[0], k1);
            mma_f16(c0, qh[1], k0 + 2);
            mma_f16(c1, qh[1], k1 + 2);

            float2 ba = *(const float2*)&brow[pj*16 + cp];
            float2 bb = *(const float2*)&brow[pj*16 + 8 + cp];
            sum0 += fexp2(fmaf(c0[0], C1, ba.x)) + fexp2(fmaf(c0[1], C1, ba.y))
                  + fexp2(fmaf(c1[0], C1, bb.x)) + fexp2(fmaf(c1[1], C1, bb.y));
            sum1 += fexp2(fmaf(c0[2], C1, ba.x)) + fexp2(fmaf(c0[3], C1, ba.y))
                  + fexp2(fmaf(c1[2], C1, bb.x)) + fexp2(fmaf(c1[3], C1, bb.y));
        }
        __syncthreads();
    }

    sum0 += __shfl_xor_sync(0xffffffffu, sum0, 1);
    sum0 += __shfl_xor_sync(0xffffffffu, sum0, 2);
    sum1 += __shfl_xor_sync(0xffffffffu, sum1, 1);
    sum1 += __shfl_xor_sync(0xffffffffu, sum1, 2);
    if ((lane & 3) == 0) {
        g_nls[nh*L_S + qr0 + wr + gid]     = -__log2f(sum0);
        g_nls[nh*L_S + qr0 + wr + gid + 8] = -__log2f(sum1);
    }
}

/* ------- kernel 3: recompute S, write attn_w, O = P @ V ------- */
__global__ __launch_bounds__(256, 2) void attn_kernel(const int* __restrict__ mask,
                                                      float* __restrict__ attn_out,
                                                      int write_attn)
{
    extern __shared__ char smem[];
    uint32_t sb = smem_u32(smem);
    int t = threadIdx.x, lane = t & 31, w = t >> 5;
    int gid = lane >> 2, cp = (lane & 3)*2, wr = w*16;
    int nh = blockIdx.y, n = nh >> 2, qt = blockIdx.x, qr0 = qt * TM;
    const int* mrow = mask + n*L_S;
    float* bias = (float*)(smem + A_BIAS);
    float* Ag = attn_out ? attn_out + (size_t)nh*L_S*L_S : (float*)0;

    const uint4* Qh = g_imgQh + (size_t)(nh*NKT + qt)*TILE_U4;
    const uint4* Ql = g_imgQl + (size_t)(nh*NKT + qt)*TILE_U4;
    const uint4* Kh = g_imgKh + (size_t)nh*NKT*TILE_U4;
    const uint4* Kl = g_imgKl + (size_t)nh*NKT*TILE_U4;
    const uint4* Vt = g_imgVt + (size_t)nh*NKT*TILE_U4;

    float nls0 = g_nls[nh*L_S + qr0 + wr + gid];
    float nls1 = g_nls[nh*L_S + qr0 + wr + gid + 8];

    /* prologue: Q hi/lo + stage0 */
    #pragma unroll
    for (int i = 0; i < 2; i++) {
        int it2 = t + i*256;
        CPA16(sb + A_QHI + it2*16, Qh + it2);
        CPA16(sb + A_QLO + it2*16, Ql + it2);
        CPA16(sb + A_STG + it2*16,          Kh + it2);
        CPA16(sb + A_STG + 8192 + it2*16,   Kl + it2);
        CPA16(sb + A_STG + 16384 + it2*16,  Vt + it2);
    }
    CPA_COMMIT();
    #pragma unroll
    for (int i = 0; i < 16; i++) {
        int idx = t + i*256;
        bias[idx] = mrow[idx] ? 0.f : MASK_B2;
    }
    CPA_WAIT(0);
    __syncthreads();

    uint32_t qh[2][4], ql[2][4];
    q_frags(sb + A_QHI, wr, lane, qh);
    q_frags(sb + A_QLO, wr, lane, ql);

    float o[4][4];
    #pragma unroll
    for (int jd = 0; jd < 4; jd++)
        #pragma unroll
        for (int i = 0; i < 4; i++) o[jd][i] = 0.f;

    float* Arow0 = Ag ? Ag + (size_t)(qr0 + wr + gid)*L_S : (float*)0;
    float* Arow1 = Ag ? Ag + (size_t)(qr0 + wr + gid + 8)*L_S : (float*)0;

    int kq = lane >> 3;
    uint32_t koff = kq*PSQ + (lane&7)*16;
    uint32_t voff = (kq & 1)*PSV + ((kq >> 1)*8 + (lane&7))*16;

    for (int kt = 0; kt < NKT; kt++) {
        if (kt + 1 < NKT) {
            uint32_t st = sb + A_STG + ((kt+1)&1)*A_STGSZ;
            size_t ti = (size_t)(kt+1)*TILE_U4;
            #pragma unroll
            for (int i = 0; i < 2; i++) {
                int it2 = t + i*256;
                CPA16(st + it2*16,          Kh + ti + it2);
                CPA16(st + 8192 + it2*16,   Kl + ti + it2);
                CPA16(st + 16384 + it2*16,  Vt + ti + it2);
            }
        }
        CPA_COMMIT();
        CPA_WAIT(1);
        __syncthreads();

        uint32_t stg = sb + A_STG + (kt&1)*A_STGSZ;
        uint32_t kbh = stg + koff;
        uint32_t kbl = stg + 8192 + koff;
        uint32_t vbase = stg + 16384;
        const float* brow = bias + kt*TK;

        #pragma unroll 1
        for (int pj = 0; pj < 8; pj++) {
            uint32_t kh0[4], kh1[4], kl0[4], kl1[4];
            LDMX4(kh0, kbh + (pj*2)*128);
            LDMX4(kh1, kbh + (pj*2+1)*128);
            LDMX4(kl0, kbl + (pj*2)*128);
            LDMX4(kl1, kbl + (pj*2+1)*128);

            float c0[4] = {0.f,0.f,0.f,0.f};
            float c1[4] = {0.f,0.f,0.f,0.f};
            #pragma unroll
            for (int ks = 0; ks < 2; ks++) {
                mma_f16(c0, qh[ks], kh0 + ks*2);
                mma_f16(c1, qh[ks], kh1 + ks*2);
                mma_f16(c0, qh[ks], kl0 + ks*2);
                mma_f16(c1, qh[ks], kl1 + ks*2);
                mma_f16(c0, ql[ks], kh0 + ks*2);
                mma_f16(c1, ql[ks], kh1 + ks*2);
            }

            float2 ba = *(const float2*)&brow[pj*16 + cp];
            float2 bb = *(const float2*)&brow[pj*16 + 8 + cp];
            float p0 = fexp2(fmaf(c0[0], C1, ba.x + nls0));
            float p1 = fexp2(fmaf(c0[1], C1, ba.y + nls0));
            float p2 = fexp2(fmaf(c0[2], C1, ba.x + nls1));
            float p3 = fexp2(fmaf(c0[3], C1, ba.y + nls1));
            float p4 = fexp2(fmaf(c1[0], C1, bb.x + nls0));
            float p5 = fexp2(fmaf(c1[1], C1, bb.y + nls0));
            float p6 = fexp2(fmaf(c1[2], C1, bb.x + nls1));
            float p7 = fexp2(fmaf(c1[3], C1, bb.y + nls1));

            if (write_attn) {
                int cb = kt*TK + pj*16 + cp;
                *(float2*)&Arow0[cb]     = make_float2(p0, p1);
                *(float2*)&Arow1[cb]     = make_float2(p2, p3);
                *(float2*)&Arow0[cb + 8] = make_float2(p4, p5);
                *(float2*)&Arow1[cb + 8] = make_float2(p6, p7);
            }

            uint32_t ah[4], al[4];
            __half2 h;
            h = __floats2half2_rn(p0, p1); ah[0] = h2bits(h);
            al[0] = h2bits(__floats2half2_rn(p0 - __half2float(__low2half(h)),
                                             p1 - __half2float(__high2half(h))));
            h = __floats2half2_rn(p2, p3); ah[1] = h2bits(h);
            al[1] = h2bits(__floats2half2_rn(p2 - __half2float(__low2half(h)),
                                             p3 - __half2float(__high2half(h))));
            h = __floats2half2_rn(p4, p5); ah[2] = h2bits(h);
            al[2] = h2bits(__floats2half2_rn(p4 - __half2float(__low2half(h)),
                                             p5 - __half2float(__high2half(h))));
            h = __floats2half2_rn(p6, p7); ah[3] = h2bits(h);
            al[3] = h2bits(__floats2half2_rn(p6 - __half2float(__low2half(h)),
                                             p7 - __half2float(__high2half(h))));

            uint32_t va[4], vb2[4];
            LDMX4(va,  vbase + (2*pj)*PSV + voff);
            LDMX4(vb2, vbase + (2*pj)*PSV + voff + 256);

            mma_f16(o[0], ah, va);
            mma_f16(o[1], ah, va + 2);
            mma_f16(o[2], ah, vb2);
            mma_f16(o[3], ah, vb2 + 2);
            mma_f16(o[0], al, va);
            mma_f16(o[1], al, va + 2);
            mma_f16(o[2], al, vb2);
            mma_f16(o[3], al, vb2 + 2);
        }
        __syncthreads();
    }

    float* Og0 = g_O + (size_t)(nh*L_S + qr0 + wr + gid)*D_H;
    float* Og1 = g_O + (size_t)(nh*L_S + qr0 + wr + gid + 8)*D_H;
    #pragma unroll
    for (int jd = 0; jd < 4; jd++) {
        int col = jd*8 + cp;
        *(float2*)&Og0[col] = make_float2(o[jd][0], o[jd][1]);
        *(float2*)&Og1[col] = make_float2(o[jd][2], o[jd][3]);
    }
}

/* ------- kernel 4: out = concat(O) @ Wo^T + bo ------- */
__global__ __launch_bounds__(256) void outproj_kernel(const float* __restrict__ Wo,
                                                      const float* __restrict__ bo,
                                                      float* __restrict__ out)
{
    __shared__ float Xs[32][EMB+1];
    __shared__ float Wsm[32][EMB+1];
    int t = threadIdx.x;
    int row0 = blockIdx.x * 32;

    for (int idx = t; idx < 32*EMB; idx += 256) {
        int r = idx >> 7, f = idx & 127;
        int row = row0 + r;
        int n = row >> 12, l = row & 4095;
        Xs[r][f] = g_O[(((size_t)n*H_N + (f>>5))*L_S + l)*D_H + (f & 31)];
    }

    int eg = t & 7;
    int r  = t >> 3;
    for (int et = 0; et < 4; et++) {
        __syncthreads();
        for (int idx = t; idx < 32*EMB; idx += 256) {
            int e = idx >> 7, f = idx & 127;
            Wsm[e][f] = Wo[(size_t)(et*32 + e)*EMB + f];
        }
        __syncthreads();
        float acc[4] = {0.f, 0.f, 0.f, 0.f};
        for (int f = 0; f < EMB; f++) {
            float x = Xs[r][f];
            #pragma unroll
            for (int j = 0; j < 4; j++) acc[j] += x * Wsm[eg*4 + j][f];
        }
        #pragma unroll
        for (int j = 0; j < 4; j++) {
            int e = et*32 + eg*4 + j;
            out[(size_t)(row0 + r)*EMB + e] = acc[j] + bo[e];
        }
    }
}

/* ---------------- launch ---------------- */
extern "C" void kernel_launch(void* const* d_in, const int* in_sizes, int n_in,
                              void* d_out, int out_size)
{
    const float* values = (const float*)d_in[0];
    const float* keys   = (const float*)d_in[1];
    const float* query  = (const float*)d_in[2];
    const int*   mask   = (const int*)d_in[3];
    const float* Wv     = (const float*)d_in[4];
    const float* Wk     = (const float*)d_in[5];
    const float* Wq     = (const float*)d_in[6];
    const float* Wo     = (const float*)d_in[7];
    const float* bo     = (const float*)d_in[8];
    float* out = (float*)d_out;

    const long long out_elems  = (long long)N_B * L_S * EMB;
    const long long attn_elems = (long long)N_B * H_N * L_S * L_S;
    int has_attn = ((long long)out_size >= out_elems + attn_elems);
    float* attn_out = has_attn ? (out + out_elems) : (float*)0;

    cudaFuncSetAttribute(stats_kernel, cudaFuncAttributeMaxDynamicSharedMemorySize, SMEM_STATS);
    cudaFuncSetAttribute(attn_kernel,  cudaFuncAttributeMaxDynamicSharedMemorySize, SMEM_ATTN);

    proj_kernel<<<(N_B*L_S*H_N)/256, 256>>>(values, keys, query, Wv, Wk, Wq);

    dim3 gc(NKT, NH);
    conv_kernel<<<gc, 256>>>();

    dim3 g(L_S/TM, NH);
    stats_kernel<<<g, 256, SMEM_STATS>>>(mask);
    attn_kernel<<<g, 256, SMEM_ATTN>>>(mask, attn_out, has_attn);

    outproj_kernel<<<(N_B*L_S)/32, 256>>>(Wo, bo, out);
}

// round 8
// speedup vs baseline: 4.7805x; 1.4765x over previous
#include <cuda_runtime.h>
#include <cuda_fp16.h>
#include <math.h>
#include <stdint.h>

#define N_B 4
#define L_S 4096
#define EMB 128
#define H_N 4
#define D_H 32
#define C1 0.12751744766f       /* (1/sqrt(128)) * log2(e) */

#define TM 128
#define TK 128
#define NKT (L_S/TK)
#define NH (N_B*H_N)

#define PSQ 2048               /* QK image: 4 d-octet planes of [128 rows][16B] */
#define PSV 512                /* V image: 16 key-octet planes of [32 d][16B]   */
#define TILE_U4 512            /* 8192 bytes per tile image */

/* attn smem offsets: Q(8K) + 2 stages x (Kh 8K + Vt 8K) + maskbits */
#define A_QHI 0
#define A_STG 8192
#define A_STGSZ 16384
#define A_MW  40960
#define SMEM_ATTN (A_MW + 512)
/* stats smem offsets */
#define S_QHI 0
#define S_STG 8192
#define S_MW  24576
#define SMEM_STATS (S_MW + 512)

/* ---------------- scratch ---------------- */
__device__ float g_Q[NH*L_S*D_H];
__device__ float g_K[NH*L_S*D_H];
__device__ float g_V[NH*L_S*D_H];
__device__ float g_O[NH*L_S*D_H];
__device__ float g_nls[NH*L_S];
__device__ uint4 g_imgQh[NH*NKT*TILE_U4];
__device__ uint4 g_imgKh[NH*NKT*TILE_U4];
__device__ uint4 g_imgVt[NH*NKT*TILE_U4];

/* ---------------- helpers ---------------- */
__device__ __forceinline__ uint32_t smem_u32(const void* p){
    uint32_t a;
    asm("{ .reg .u64 t; cvta.to.shared.u64 t, %1; cvt.u32.u64 %0, t; }" : "=r"(a) : "l"(p));
    return a;
}
__device__ __forceinline__ void mma_f16(float* c, const uint32_t* a, const uint32_t* b){
    asm volatile("mma.sync.aligned.m16n8k16.row.col.f32.f16.f16.f32 "
        "{%0,%1,%2,%3}, {%4,%5,%6,%7}, {%8,%9}, {%0,%1,%2,%3};"
        : "+f"(c[0]), "+f"(c[1]), "+f"(c[2]), "+f"(c[3])
        : "r"(a[0]), "r"(a[1]), "r"(a[2]), "r"(a[3]), "r"(b[0]), "r"(b[1]));
}
#define LDMX4(r, a) \
    asm volatile("ldmatrix.sync.aligned.m8n8.x4.shared.b16 {%0,%1,%2,%3}, [%4];" \
        : "=r"((r)[0]), "=r"((r)[1]), "=r"((r)[2]), "=r"((r)[3]) : "r"(a))
#define CPA16(dst, src) \
    asm volatile("cp.async.cg.shared.global [%0], [%1], 16;" :: "r"(dst), "l"(src))
#define CPA_COMMIT() asm volatile("cp.async.commit_group;" ::: "memory")
#define CPA_WAIT(n)  asm volatile("cp.async.wait_group %0;" :: "n"(n) : "memory")

__device__ __forceinline__ float ex2a(float x){
    float r;
    asm("ex2.approx.f32 %0, %1;" : "=f"(r) : "f"(x));
    return r;
}
__device__ __forceinline__ uint32_t h2bits(__half2 v){
    return *reinterpret_cast<uint32_t*>(&v);
}

__device__ __forceinline__ void q_frags(uint32_t base, int wr, int lane, uint32_t qf[2][4])
{
    int m = lane >> 3;
    int row = wr + (m & 1)*8 + (lane & 7);
    uint32_t a0 = base + (m >> 1)*PSQ + row*16;
    LDMX4(qf[0], a0);
    LDMX4(qf[1], a0 + 2*PSQ);
}

/* ---------------- kernel 1: per-head input projections ---------------- */
__global__ __launch_bounds__(256) void proj_kernel(
    const float* __restrict__ vin, const float* __restrict__ kin,
    const float* __restrict__ qin,
    const float* __restrict__ Wv, const float* __restrict__ Wk,
    const float* __restrict__ Wq)
{
    __shared__ float Ws[3][D_H*D_H];
    int t = threadIdx.x;
    for (int i = t; i < D_H*D_H; i += 256) {
        Ws[0][i] = Wq[i]; Ws[1][i] = Wk[i]; Ws[2][i] = Wv[i];
    }
    __syncthreads();

    int gid = blockIdx.x * 256 + t;
    int h  = gid & (H_N-1);
    int nl = gid >> 2;
    int n  = nl >> 12;
    int l  = nl & (L_S-1);
    size_t inbase  = (size_t)nl * EMB + h * D_H;
    size_t outbase = (((size_t)(n*H_N + h)) * L_S + l) * D_H;

    const float* ins[3]  = {qin, kin, vin};
    float*       outs[3] = {g_Q, g_K, g_V};

    for (int mm = 0; mm < 3; mm++) {
        float x[D_H];
        #pragma unroll
        for (int i = 0; i < D_H/4; i++)
            *(float4*)&x[i*4] = *(const float4*)&ins[mm][inbase + i*4];
        #pragma unroll 4
        for (int e = 0; e < D_H; e++) {
            float a = 0.f;
            #pragma unroll
            for (int d = 0; d < D_H; d++) a += x[d] * Ws[mm][e*D_H + d];
            outs[mm][outbase + e] = a;
        }
    }
}

/* ------- kernel 1b: build fp16 tile images (hi only) ------- */
__global__ __launch_bounds__(256) void conv_kernel()
{
    __shared__ float tile[128*33];
    int t = threadIdx.x;
    int kt = blockIdx.x, nh = blockIdx.y;
    size_t src = ((size_t)nh*L_S + (size_t)kt*128) * D_H;
    size_t ti = (size_t)(nh*NKT + kt) * TILE_U4;

    const float* srcs[2] = { g_Q + src, g_K + src };
    uint4* dsts[2] = { g_imgQh + ti, g_imgKh + ti };
    for (int mm = 0; mm < 2; mm++) {
        __syncthreads();
        for (int idx = t; idx < 1024; idx += 256) {
            int r = idx >> 3, c4 = idx & 7;
            float4 x = *(const float4*)&srcs[mm][(size_t)r*32 + c4*4];
            float* drow = &tile[r*33 + c4*4];
            drow[0] = x.x; drow[1] = x.y; drow[2] = x.z; drow[3] = x.w;
        }
        __syncthreads();
        #pragma unroll
        for (int i = 0; i < 2; i++) {
            int item = t + i*256;
            int p = item >> 7, r = item & 127;
            const float* row = &tile[r*33 + p*8];
            uint32_t hw[4];
            #pragma unroll
            for (int w2 = 0; w2 < 4; w2++)
                hw[w2] = h2bits(__floats2half2_rn(row[w2*2], row[w2*2+1]));
            dsts[mm][item] = make_uint4(hw[0], hw[1], hw[2], hw[3]);
        }
    }

    __syncthreads();
    for (int idx = t; idx < 1024; idx += 256) {
        int r = idx >> 3, c4 = idx & 7;
        float4 x = *(const float4*)&g_V[src + (size_t)r*32 + c4*4];
        float* drow = &tile[r*33 + c4*4];
        drow[0] = x.x; drow[1] = x.y; drow[2] = x.z; drow[3] = x.w;
    }
    __syncthreads();
    #pragma unroll
    for (int i = 0; i < 2; i++) {
        int item = t + i*256;
        int oct = item >> 5, d = item & 31;
        uint32_t w[4];
        #pragma unroll
        for (int w2 = 0; w2 < 4; w2++) {
            float x0 = tile[(oct*8 + w2*2)*33 + d];
            float x1 = tile[(oct*8 + w2*2 + 1)*33 + d];
            w[w2] = h2bits(__floats2half2_rn(x0, x1));
        }
        g_imgVt[ti + item] = make_uint4(w[0], w[1], w[2], w[3]);
    }
}

/* ------- kernel 2: row sums via fp16 HMMA QK^T ------- */
__global__ __launch_bounds__(256, 4) void stats_kernel(const int* __restrict__ mask)
{
    extern __shared__ char smem[];
    uint32_t sb = smem_u32(smem);
    int t = threadIdx.x, lane = t & 31, w = t >> 5;
    int gid = lane >> 2, cp = (lane & 3)*2, wr = w*16;
    int nh = blockIdx.y, n = nh >> 2, qt = blockIdx.x, qr0 = qt * TM;
    const int* mrow = mask + n*L_S;
    uint32_t* mw = (uint32_t*)(smem + S_MW);

    const uint4* Qh = g_imgQh + (size_t)(nh*NKT + qt)*TILE_U4;
    const uint4* Kh = g_imgKh + (size_t)nh*NKT*TILE_U4;

    #pragma unroll
    for (int i = 0; i < 2; i++) {
        CPA16(sb + S_QHI + (t + i*256)*16, Qh + t + i*256);
        CPA16(sb + S_STG + (t + i*256)*16, Kh + t + i*256);
    }
    CPA_COMMIT();
    if (t < 128) {
        uint32_t wbits = 0;
        const int* mp = mrow + t*32;
        #pragma unroll 8
        for (int j = 0; j < 32; j++) wbits |= (mp[j] ? 1u : 0u) << j;
        mw[t] = wbits;
    }
    CPA_WAIT(0);
    __syncthreads();

    uint32_t qh[2][4];
    q_frags(sb + S_QHI, wr, lane, qh);

    float sum0 = 0.f, sum1 = 0.f;

    for (int kt = 0; kt < NKT; kt++) {
        if (kt + 1 < NKT) {
            uint32_t st = sb + S_STG + ((kt+1)&1)*8192;
            const uint4* src = Kh + (size_t)(kt+1)*TILE_U4;
            CPA16(st + t*16, src + t);
            CPA16(st + (t+256)*16, src + t + 256);
        }
        CPA_COMMIT();
        CPA_WAIT(1);
        __syncthreads();

        uint32_t kb = sb + S_STG + (kt&1)*8192 + (lane>>3)*PSQ + (lane&7)*16;

        #pragma unroll 2
        for (int pj = 0; pj < 8; pj++) {
            uint32_t k0[4], k1[4];
            LDMX4(k0, kb + (pj*2)*128);
            LDMX4(k1, kb + (pj*2+1)*128);
            float c0[4] = {0.f,0.f,0.f,0.f};
            float c1[4] = {0.f,0.f,0.f,0.f};
            mma_f16(c0, qh[0], k0);
            mma_f16(c1, qh[0], k1);
            mma_f16(c0, qh[1], k0 + 2);
            mma_f16(c1, qh[1], k1 + 2);

            uint32_t gw = mw[(kt<<2) + (pj>>1)] >> ((pj&1)<<4);
            bool b0 = gw & (1u<<cp);
            bool b1 = gw & (1u<<(cp+1));
            bool b2 = gw & (1u<<(cp+8));
            bool b3 = gw & (1u<<(cp+9));
            float e0 = ex2a(c0[0]*C1), e1 = ex2a(c0[1]*C1);
            float e2 = ex2a(c0[2]*C1), e3 = ex2a(c0[3]*C1);
            float e4 = ex2a(c1[0]*C1), e5 = ex2a(c1[1]*C1);
            float e6 = ex2a(c1[2]*C1), e7 = ex2a(c1[3]*C1);
            sum0 += (b0 ? e0 : 0.f) + (b1 ? e1 : 0.f) + (b2 ? e4 : 0.f) + (b3 ? e5 : 0.f);
            sum1 += (b0 ? e2 : 0.f) + (b1 ? e3 : 0.f) + (b2 ? e6 : 0.f) + (b3 ? e7 : 0.f);
        }
        __syncthreads();
    }

    sum0 += __shfl_xor_sync(0xffffffffu, sum0, 1);
    sum0 += __shfl_xor_sync(0xffffffffu, sum0, 2);
    sum1 += __shfl_xor_sync(0xffffffffu, sum1, 1);
    sum1 += __shfl_xor_sync(0xffffffffu, sum1, 2);
    if ((lane & 3) == 0) {
        g_nls[nh*L_S + qr0 + wr + gid]     = -__log2f(sum0);
        g_nls[nh*L_S + qr0 + wr + gid + 8] = -__log2f(sum1);
    }
}

/* ------- kernel 3: recompute S, write attn_w, O = P @ V ------- */
__global__ __launch_bounds__(256, 3) void attn_kernel(const int* __restrict__ mask,
                                                      float* __restrict__ attn_out,
                                                      int write_attn)
{
    extern __shared__ char smem[];
    uint32_t sb = smem_u32(smem);
    int t = threadIdx.x, lane = t & 31, w = t >> 5;
    int gid = lane >> 2, cp = (lane & 3)*2, wr = w*16;
    int nh = blockIdx.y, n = nh >> 2, qt = blockIdx.x, qr0 = qt * TM;
    const int* mrow = mask + n*L_S;
    uint32_t* mw = (uint32_t*)(smem + A_MW);
    float* Ag = attn_out ? attn_out + (size_t)nh*L_S*L_S : (float*)0;

    const uint4* Qh = g_imgQh + (size_t)(nh*NKT + qt)*TILE_U4;
    const uint4* Kh = g_imgKh + (size_t)nh*NKT*TILE_U4;
    const uint4* Vt = g_imgVt + (size_t)nh*NKT*TILE_U4;

    float nls0 = g_nls[nh*L_S + qr0 + wr + gid];
    float nls1 = g_nls[nh*L_S + qr0 + wr + gid + 8];

    #pragma unroll
    for (int i = 0; i < 2; i++) {
        int it2 = t + i*256;
        CPA16(sb + A_QHI + it2*16, Qh + it2);
        CPA16(sb + A_STG + it2*16,        Kh + it2);
        CPA16(sb + A_STG + 8192 + it2*16, Vt + it2);
    }
    CPA_COMMIT();
    if (t < 128) {
        uint32_t wbits = 0;
        const int* mp = mrow + t*32;
        #pragma unroll 8
        for (int j = 0; j < 32; j++) wbits |= (mp[j] ? 1u : 0u) << j;
        mw[t] = wbits;
    }
    CPA_WAIT(0);
    __syncthreads();

    uint32_t qh[2][4];
    q_frags(sb + A_QHI, wr, lane, qh);

    float o[4][4];
    #pragma unroll
    for (int jd = 0; jd < 4; jd++)
        #pragma unroll
        for (int i = 0; i < 4; i++) o[jd][i] = 0.f;

    float* Arow0 = Ag ? Ag + (size_t)(qr0 + wr + gid)*L_S : (float*)0;
    float* Arow1 = Ag ? Ag + (size_t)(qr0 + wr + gid + 8)*L_S : (float*)0;

    int kq = lane >> 3;
    uint32_t koff = kq*PSQ + (lane&7)*16;
    uint32_t voff = (kq & 1)*PSV + ((kq >> 1)*8 + (lane&7))*16;

    for (int kt = 0; kt < NKT; kt++) {
        if (kt + 1 < NKT) {
            uint32_t st = sb + A_STG + ((kt+1)&1)*A_STGSZ;
            size_t ti = (size_t)(kt+1)*TILE_U4;
            #pragma unroll
            for (int i = 0; i < 2; i++) {
                int it2 = t + i*256;
                CPA16(st + it2*16,        Kh + ti + it2);
                CPA16(st + 8192 + it2*16, Vt + ti + it2);
            }
        }
        CPA_COMMIT();
        CPA_WAIT(1);
        __syncthreads();

        uint32_t stg = sb + A_STG + (kt&1)*A_STGSZ;
        uint32_t kbh = stg + koff;
        uint32_t vbase = stg + 8192;

        #pragma unroll 1
        for (int pj = 0; pj < 8; pj++) {
            uint32_t k0[4], k1[4];
            LDMX4(k0, kbh + (pj*2)*128);
            LDMX4(k1, kbh + (pj*2+1)*128);

            float c0[4] = {0.f,0.f,0.f,0.f};
            float c1[4] = {0.f,0.f,0.f,0.f};
            mma_f16(c0, qh[0], k0);
            mma_f16(c1, qh[0], k1);
            mma_f16(c0, qh[1], k0 + 2);
            mma_f16(c1, qh[1], k1 + 2);

            uint32_t gw = mw[(kt<<2) + (pj>>1)] >> ((pj&1)<<4);
            bool b0 = gw & (1u<<cp);
            bool b1 = gw & (1u<<(cp+1));
            bool b2 = gw & (1u<<(cp+8));
            bool b3 = gw & (1u<<(cp+9));

            float p0 = b0 ? ex2a(fmaf(c0[0], C1, nls0)) : 0.f;
            float p1 = b1 ? ex2a(fmaf(c0[1], C1, nls0)) : 0.f;
            float p2 = b0 ? ex2a(fmaf(c0[2], C1, nls1)) : 0.f;
            float p3 = b1 ? ex2a(fmaf(c0[3], C1, nls1)) : 0.f;
            float p4 = b2 ? ex2a(fmaf(c1[0], C1, nls0)) : 0.f;
            float p5 = b3 ? ex2a(fmaf(c1[1], C1, nls0)) : 0.f;
            float p6 = b2 ? ex2a(fmaf(c1[2], C1, nls1)) : 0.f;
            float p7 = b3 ? ex2a(fmaf(c1[3], C1, nls1)) : 0.f;

            if (write_attn) {
                int cb = kt*TK + pj*16 + cp;
                *(float2*)&Arow0[cb]     = make_float2(p0, p1);
                *(float2*)&Arow1[cb]     = make_float2(p2, p3);
                *(float2*)&Arow0[cb + 8] = make_float2(p4, p5);
                *(float2*)&Arow1[cb + 8] = make_float2(p6, p7);
            }

            uint32_t ah[4];
            ah[0] = h2bits(__floats2half2_rn(p0, p1));
            ah[1] = h2bits(__floats2half2_rn(p2, p3));
            ah[2] = h2bits(__floats2half2_rn(p4, p5));
            ah[3] = h2bits(__floats2half2_rn(p6, p7));

            uint32_t va[4], vb2[4];
            LDMX4(va,  vbase + (2*pj)*PSV + voff);
            LDMX4(vb2, vbase + (2*pj)*PSV + voff + 256);

            mma_f16(o[0], ah, va);
            mma_f16(o[1], ah, va + 2);
            mma_f16(o[2], ah, vb2);
            mma_f16(o[3], ah, vb2 + 2);
        }
        __syncthreads();
    }

    float* Og0 = g_O + (size_t)(nh*L_S + qr0 + wr + gid)*D_H;
    float* Og1 = g_O + (size_t)(nh*L_S + qr0 + wr + gid + 8)*D_H;
    #pragma unroll
    for (int jd = 0; jd < 4; jd++) {
        int col = jd*8 + cp;
        *(float2*)&Og0[col] = make_float2(o[jd][0], o[jd][1]);
        *(float2*)&Og1[col] = make_float2(o[jd][2], o[jd][3]);
    }
}

/* ------- kernel 4: out = concat(O) @ Wo^T + bo (register-tiled) ------- */
#define OP_PITCH 132
__global__ __launch_bounds__(256) void outproj_kernel(const float* __restrict__ Wo,
                                                      const float* __restrict__ bo,
                                                      float* __restrict__ out)
{
    __shared__ float Xs[64*OP_PITCH];
    __shared__ float Wsm[64*OP_PITCH];
    int t = threadIdx.x;
    int row0 = blockIdx.x * 64;
    int eg = t & 7;
    int rt = t >> 3;            /* 0..31, rows rt*2, rt*2+1 */

    for (int idx = t; idx < 64*32; idx += 256) {
        int r = idx >> 5, c4 = idx & 31;
        int row = row0 + r;
        int n = row >> 12, l = row & 4095;
        int f0 = c4*4;
        float4 v = make_float4(
            g_O[(((size_t)n*H_N + (f0>>5))*L_S + l)*D_H + (f0 & 31)],
            g_O[(((size_t)n*H_N + ((f0+1)>>5))*L_S + l)*D_H + ((f0+1) & 31)],
            g_O[(((size_t)n*H_N + ((f0+2)>>5))*L_S + l)*D_H + ((f0+2) & 31)],
            g_O[(((size_t)n*H_N + ((f0+3)>>5))*L_S + l)*D_H + ((f0+3) & 31)]);
        *(float4*)&Xs[r*OP_PITCH + f0] = v;
    }

    for (int et = 0; et < 2; et++) {
        __syncthreads();
        for (int idx = t; idx < 64*32; idx += 256) {
            int e = idx >> 5, c4 = idx & 31;
            *(float4*)&Wsm[e*OP_PITCH + c4*4] =
                *(const float4*)&Wo[(size_t)(et*64 + e)*EMB + c4*4];
        }
        __syncthreads();

        float acc[2][8];
        #pragma unroll
        for (int r = 0; r < 2; r++)
            #pragma unroll
            for (int j = 0; j < 8; j++) acc[r][j] = 0.f;

        const float* x0 = &Xs[(rt*2)*OP_PITCH];
        const float* x1 = &Xs[(rt*2+1)*OP_PITCH];
        #pragma unroll 4
        for (int f = 0; f < EMB; f++) {
            float a0 = x0[f], a1 = x1[f];
            #pragma unroll
            for (int j = 0; j < 8; j++) {
                float wv = Wsm[(j*8 + eg)*OP_PITCH + f];
                acc[0][j] += a0 * wv;
                acc[1][j] += a1 * wv;
            }
        }

        #pragma unroll
        for (int r = 0; r < 2; r++) {
            int row = row0 + rt*2 + r;
            #pragma unroll
            for (int j = 0; j < 8; j++) {
                int e = et*64 + j*8 + eg;
                out[(size_t)row*EMB + e] = acc[r][j] + bo[e];
            }
        }
    }
}

/* ---------------- launch ---------------- */
extern "C" void kernel_launch(void* const* d_in, const int* in_sizes, int n_in,
                              void* d_out, int out_size)
{
    const float* values = (const float*)d_in[0];
    const float* keys   = (const float*)d_in[1];
    const float* query  = (const float*)d_in[2];
    const int*   mask   = (const int*)d_in[3];
    const float* Wv     = (const float*)d_in[4];
    const float* Wk     = (const float*)d_in[5];
    const float* Wq     = (const float*)d_in[6];
    const float* Wo     = (const float*)d_in[7];
    const float* bo     = (const float*)d_in[8];
    float* out = (float*)d_out;

    const long long out_elems  = (long long)N_B * L_S * EMB;
    const long long attn_elems = (long long)N_B * H_N * L_S * L_S;
    int has_attn = ((long long)out_size >= out_elems + attn_elems);
    float* attn_out = has_attn ? (out + out_elems) : (float*)0;

    cudaFuncSetAttribute(stats_kernel, cudaFuncAttributeMaxDynamicSharedMemorySize, SMEM_STATS);
    cudaFuncSetAttribute(attn_kernel,  cudaFuncAttributeMaxDynamicSharedMemorySize, SMEM_ATTN);

    proj_kernel<<<(N_B*L_S*H_N)/256, 256>>>(values, keys, query, Wv, Wk, Wq);

    dim3 gc(NKT, NH);
    conv_kernel<<<gc, 256>>>();

    dim3 g(L_S/TM, NH);
    stats_kernel<<<g, 256, SMEM_STATS>>>(mask);
    attn_kernel<<<g, 256, SMEM_ATTN>>>(mask, attn_out, has_attn);

    outproj_kernel<<<(N_B*L_S)/64, 256>>>(Wo, bo, out);
}

// round 9
// speedup vs baseline: 4.8028x; 1.0047x over previous
#include <cuda_runtime.h>
#include <cuda_fp16.h>
#include <math.h>
#include <stdint.h>

#define N_B 4
#define L_S 4096
#define EMB 128
#define H_N 4
#define D_H 32
#define C1 0.12751744766f       /* (1/sqrt(128)) * log2(e) */

#define TM 128
#define TK 128
#define NKT (L_S/TK)
#define NH (N_B*H_N)

#define PSQ 2048               /* QK image: 4 d-octet planes of [128 rows][16B] */
#define PSV 512                /* V image: 16 key-octet planes of [32 d][16B]   */
#define TILE_U4 512            /* 8192 bytes per tile image */

/* attn smem: 3 stages x (Kh 8K + Vt 8K); Q image overlays stage2 K area */
#define A_STGSZ 16384
#define A_QOVL  (2*A_STGSZ)
#define A_MW    (3*A_STGSZ)
#define SMEM_ATTN (A_MW + 512)
/* stats smem: 3 stages x (Kh 8K); Q image overlays stage2 */
#define S_STGSZ 8192
#define S_QOVL  (2*S_STGSZ)
#define S_MW    (3*S_STGSZ)
#define SMEM_STATS (S_MW + 512)

/* ---------------- scratch ---------------- */
__device__ float g_O[NH*L_S*D_H];
__device__ float g_nls[NH*L_S];
__device__ uint4 g_imgQh[NH*NKT*TILE_U4];
__device__ uint4 g_imgKh[NH*NKT*TILE_U4];
__device__ uint4 g_imgVt[NH*NKT*TILE_U4];

/* ---------------- helpers ---------------- */
__device__ __forceinline__ uint32_t smem_u32(const void* p){
    uint32_t a;
    asm("{ .reg .u64 t; cvta.to.shared.u64 t, %1; cvt.u32.u64 %0, t; }" : "=r"(a) : "l"(p));
    return a;
}
__device__ __forceinline__ void mma_f16(float* c, const uint32_t* a, const uint32_t* b){
    asm volatile("mma.sync.aligned.m16n8k16.row.col.f32.f16.f16.f32 "
        "{%0,%1,%2,%3}, {%4,%5,%6,%7}, {%8,%9}, {%0,%1,%2,%3};"
        : "+f"(c[0]), "+f"(c[1]), "+f"(c[2]), "+f"(c[3])
        : "r"(a[0]), "r"(a[1]), "r"(a[2]), "r"(a[3]), "r"(b[0]), "r"(b[1]));
}
#define LDMX4(r, a) \
    asm volatile("ldmatrix.sync.aligned.m8n8.x4.shared.b16 {%0,%1,%2,%3}, [%4];" \
        : "=r"((r)[0]), "=r"((r)[1]), "=r"((r)[2]), "=r"((r)[3]) : "r"(a))
#define CPA16(dst, src) \
    asm volatile("cp.async.cg.shared.global [%0], [%1], 16;" :: "r"(dst), "l"(src))
#define CPA_COMMIT() asm volatile("cp.async.commit_group;" ::: "memory")
#define CPA_WAIT(n)  asm volatile("cp.async.wait_group %0;" :: "n"(n) : "memory")

__device__ __forceinline__ float ex2a(float x){
    float r;
    asm("ex2.approx.f32 %0, %1;" : "=f"(r) : "f"(x));
    return r;
}
__device__ __forceinline__ uint32_t h2bits(__half2 v){
    return *reinterpret_cast<uint32_t*>(&v);
}

__device__ __forceinline__ void q_frags(uint32_t base, int wr, int lane, uint32_t qf[2][4])
{
    int m = lane >> 3;
    int row = wr + (m & 1)*8 + (lane & 7);
    uint32_t a0 = base + (m >> 1)*PSQ + row*16;
    LDMX4(qf[0], a0);
    LDMX4(qf[1], a0 + 2*PSQ);
}

/* ------- kernel 1: fused projection + fp16 image build ------- */
/* grid (NKT, NH); one (head, 128-row tile) per CTA */
__global__ __launch_bounds__(256) void projconv_kernel(
    const float* __restrict__ vin, const float* __restrict__ kin,
    const float* __restrict__ qin,
    const float* __restrict__ Wv, const float* __restrict__ Wk,
    const float* __restrict__ Wq)
{
    __shared__ float Ws[3][D_H*33];
    __shared__ float Xs[128*33];
    int t = threadIdx.x;
    int kt = blockIdx.x, nh = blockIdx.y;
    int n = nh >> 2, h = nh & 3;
    size_t inbase = ((size_t)n*L_S + (size_t)kt*128)*EMB + h*D_H;
    size_t ti = (size_t)(nh*NKT + kt) * TILE_U4;

    for (int i = t; i < D_H*D_H; i += 256) {
        int e = i >> 5, d = i & 31;
        Ws[0][e*33+d] = Wq[i]; Ws[1][e*33+d] = Wk[i]; Ws[2][e*33+d] = Wv[i];
    }

    const float* ins[3] = { qin, kin, vin };
    uint4* qkdst[2] = { g_imgQh + ti, g_imgKh + ti };

    int r = t & 127, half = t >> 7;          /* e range: half*16 .. half*16+15 */
    int e0 = half*16;

    for (int mm = 0; mm < 3; mm++) {
        __syncthreads();                      /* Xs free / Ws ready (first iter) */
        for (int idx = t; idx < 128*8; idx += 256) {
            int rr = idx >> 3, c4 = idx & 7;
            float4 x = *(const float4*)&ins[mm][inbase + (size_t)rr*EMB + c4*4];
            float* drow = &Xs[rr*33 + c4*4];
            drow[0] = x.x; drow[1] = x.y; drow[2] = x.z; drow[3] = x.w;
        }
        __syncthreads();

        float x[D_H];
        #pragma unroll
        for (int d = 0; d < D_H; d++) x[d] = Xs[r*33 + d];

        float o[16];
        #pragma unroll
        for (int j = 0; j < 16; j++) {
            float a = 0.f;
            const float* wrow = &Ws[mm][(e0+j)*33];
            #pragma unroll
            for (int d = 0; d < D_H; d++) a = fmaf(x[d], wrow[d], a);
            o[j] = a;
        }

        uint32_t hw[8];
        #pragma unroll
        for (int j = 0; j < 8; j++)
            hw[j] = h2bits(__floats2half2_rn(o[2*j], o[2*j+1]));

        if (mm < 2) {
            int oct0 = half*2;
            qkdst[mm][(oct0  )*128 + r] = make_uint4(hw[0], hw[1], hw[2], hw[3]);
            qkdst[mm][(oct0+1)*128 + r] = make_uint4(hw[4], hw[5], hw[6], hw[7]);
        } else {
            /* V: stash proj result, then transpose-repack */
            __syncthreads();
            float* drow = &Xs[r*33 + e0];
            #pragma unroll
            for (int j = 0; j < 16; j++) drow[j] = o[j];
            __syncthreads();
            #pragma unroll
            for (int i = 0; i < 2; i++) {
                int item = t + i*256;
                int oct = item >> 5, d = item & 31;
                uint32_t w[4];
                #pragma unroll
                for (int w2 = 0; w2 < 4; w2++) {
                    float x0 = Xs[(oct*8 + w2*2)*33 + d];
                    float x1 = Xs[(oct*8 + w2*2 + 1)*33 + d];
                    w[w2] = h2bits(__floats2half2_rn(x0, x1));
                }
                g_imgVt[ti + item] = make_uint4(w[0], w[1], w[2], w[3]);
            }
        }
    }
}

/* ------- kernel 2: row sums via fp16 HMMA QK^T ------- */
__global__ __launch_bounds__(256, 5) void stats_kernel(const int* __restrict__ mask)
{
    extern __shared__ char smem[];
    uint32_t sb = smem_u32(smem);
    int t = threadIdx.x, lane = t & 31, w = t >> 5;
    int gid = lane >> 2, cp = (lane & 3)*2, wr = w*16;
    int nh = blockIdx.y, n = nh >> 2, qt = blockIdx.x, qr0 = qt * TM;
    const int* mrow = mask + n*L_S;
    uint32_t* mw = (uint32_t*)(smem + S_MW);

    const uint4* Qh = g_imgQh + (size_t)(nh*NKT + qt)*TILE_U4;
    const uint4* Kh = g_imgKh + (size_t)nh*NKT*TILE_U4;

    /* prologue: Q (overlay in stage2) + stage0 K */
    #pragma unroll
    for (int i = 0; i < 2; i++) {
        CPA16(sb + S_QOVL + (t + i*256)*16, Qh + t + i*256);
        CPA16(sb +          (t + i*256)*16, Kh + t + i*256);
    }
    CPA_COMMIT();
    if (t < 128) {
        uint32_t wbits = 0;
        const int* mp = mrow + t*32;
        #pragma unroll 8
        for (int j = 0; j < 32; j++) wbits |= (mp[j] ? 1u : 0u) << j;
        mw[t] = wbits;
    }
    CPA_WAIT(0);
    __syncthreads();

    uint32_t qh[2][4];
    q_frags(sb + S_QOVL, wr, lane, qh);

    uint32_t koff = (lane>>3)*PSQ + (lane&7)*16;
    float sum0 = 0.f, sum1 = 0.f;
    int stg_rd = 0;

    for (int kt = 0; kt < NKT; kt++) {
        if (kt + 1 < NKT) {
            int stw = stg_rd + 1; if (stw == 3) stw = 0;
            uint32_t st = sb + stw*S_STGSZ;
            const uint4* src = Kh + (size_t)(kt+1)*TILE_U4;
            CPA16(st + t*16, src + t);
            CPA16(st + (t+256)*16, src + t + 256);
        }
        CPA_COMMIT();
        CPA_WAIT(1);
        __syncthreads();

        uint32_t kb = sb + stg_rd*S_STGSZ + koff;

        #pragma unroll 2
        for (int pj = 0; pj < 8; pj++) {
            uint32_t k0[4], k1[4];
            LDMX4(k0, kb + (pj*2)*128);
            LDMX4(k1, kb + (pj*2+1)*128);
            float c0[4] = {0.f,0.f,0.f,0.f};
            float c1[4] = {0.f,0.f,0.f,0.f};
            mma_f16(c0, qh[0], k0);
            mma_f16(c1, qh[0], k1);
            mma_f16(c0, qh[1], k0 + 2);
            mma_f16(c1, qh[1], k1 + 2);

            uint32_t gw = mw[(kt<<2) + (pj>>1)] >> ((pj&1)<<4);
            bool b0 = gw & (1u<<cp);
            bool b1 = gw & (1u<<(cp+1));
            bool b2 = gw & (1u<<(cp+8));
            bool b3 = gw & (1u<<(cp+9));
            float e0 = ex2a(c0[0]*C1), e1 = ex2a(c0[1]*C1);
            float e2 = ex2a(c0[2]*C1), e3 = ex2a(c0[3]*C1);
            float e4 = ex2a(c1[0]*C1), e5 = ex2a(c1[1]*C1);
            float e6 = ex2a(c1[2]*C1), e7 = ex2a(c1[3]*C1);
            sum0 += (b0 ? e0 : 0.f) + (b1 ? e1 : 0.f) + (b2 ? e4 : 0.f) + (b3 ? e5 : 0.f);
            sum1 += (b0 ? e2 : 0.f) + (b1 ? e3 : 0.f) + (b2 ? e6 : 0.f) + (b3 ? e7 : 0.f);
        }
        if (++stg_rd == 3) stg_rd = 0;
    }

    sum0 += __shfl_xor_sync(0xffffffffu, sum0, 1);
    sum0 += __shfl_xor_sync(0xffffffffu, sum0, 2);
    sum1 += __shfl_xor_sync(0xffffffffu, sum1, 1);
    sum1 += __shfl_xor_sync(0xffffffffu, sum1, 2);
    if ((lane & 3) == 0) {
        g_nls[nh*L_S + qr0 + wr + gid]     = -__log2f(sum0);
        g_nls[nh*L_S + qr0 + wr + gid + 8] = -__log2f(sum1);
    }
}

/* ------- kernel 3: recompute S, write attn_w, O = P @ V ------- */
__global__ __launch_bounds__(256, 4) void attn_kernel(const int* __restrict__ mask,
                                                      float* __restrict__ attn_out,
                                                      int write_attn)
{
    extern __shared__ char smem[];
    uint32_t sb = smem_u32(smem);
    int t = threadIdx.x, lane = t & 31, w = t >> 5;
    int gid = lane >> 2, cp = (lane & 3)*2, wr = w*16;
    int nh = blockIdx.y, n = nh >> 2, qt = blockIdx.x, qr0 = qt * TM;
    const int* mrow = mask + n*L_S;
    uint32_t* mw = (uint32_t*)(smem + A_MW);
    float* Ag = attn_out ? attn_out + (size_t)nh*L_S*L_S : (float*)0;

    const uint4* Qh = g_imgQh + (size_t)(nh*NKT + qt)*TILE_U4;
    const uint4* Kh = g_imgKh + (size_t)nh*NKT*TILE_U4;
    const uint4* Vt = g_imgVt + (size_t)nh*NKT*TILE_U4;

    float nls0 = g_nls[nh*L_S + qr0 + wr + gid];
    float nls1 = g_nls[nh*L_S + qr0 + wr + gid + 8];

    /* prologue: Q (overlay in stage2 K area) + stage0 K/V */
    #pragma unroll
    for (int i = 0; i < 2; i++) {
        int it2 = t + i*256;
        CPA16(sb + A_QOVL + it2*16, Qh + it2);
        CPA16(sb +          it2*16, Kh + it2);
        CPA16(sb +   8192 + it2*16, Vt + it2);
    }
    CPA_COMMIT();
    if (t < 128) {
        uint32_t wbits = 0;
        const int* mp = mrow + t*32;
        #pragma unroll 8
        for (int j = 0; j < 32; j++) wbits |= (mp[j] ? 1u : 0u) << j;
        mw[t] = wbits;
    }
    CPA_WAIT(0);
    __syncthreads();

    uint32_t qh[2][4];
    q_frags(sb + A_QOVL, wr, lane, qh);

    float o[4][4];
    #pragma unroll
    for (int jd = 0; jd < 4; jd++)
        #pragma unroll
        for (int i = 0; i < 4; i++) o[jd][i] = 0.f;

    float* Arow0 = Ag ? Ag + (size_t)(qr0 + wr + gid)*L_S : (float*)0;
    float* Arow1 = Ag ? Ag + (size_t)(qr0 + wr + gid + 8)*L_S : (float*)0;

    int kq = lane >> 3;
    uint32_t koff = kq*PSQ + (lane&7)*16;
    uint32_t voff = (kq & 1)*PSV + ((kq >> 1)*8 + (lane&7))*16;
    int stg_rd = 0;

    for (int kt = 0; kt < NKT; kt++) {
        if (kt + 1 < NKT) {
            int stw = stg_rd + 1; if (stw == 3) stw = 0;
            uint32_t st = sb + stw*A_STGSZ;
            size_t ti = (size_t)(kt+1)*TILE_U4;
            #pragma unroll
            for (int i = 0; i < 2; i++) {
                int it2 = t + i*256;
                CPA16(st + it2*16,        Kh + ti + it2);
                CPA16(st + 8192 + it2*16, Vt + ti + it2);
            }
        }
        CPA_COMMIT();
        CPA_WAIT(1);
        __syncthreads();

        uint32_t stg = sb + stg_rd*A_STGSZ;
        uint32_t kbh = stg + koff;
        uint32_t vbase = stg + 8192;

        #pragma unroll 1
        for (int pj = 0; pj < 8; pj++) {
            uint32_t k0[4], k1[4];
            LDMX4(k0, kbh + (pj*2)*128);
            LDMX4(k1, kbh + (pj*2+1)*128);

            float c0[4] = {0.f,0.f,0.f,0.f};
            float c1[4] = {0.f,0.f,0.f,0.f};
            mma_f16(c0, qh[0], k0);
            mma_f16(c1, qh[0], k1);
            mma_f16(c0, qh[1], k0 + 2);
            mma_f16(c1, qh[1], k1 + 2);

            uint32_t gw = mw[(kt<<2) + (pj>>1)] >> ((pj&1)<<4);
            bool b0 = gw & (1u<<cp);
            bool b1 = gw & (1u<<(cp+1));
            bool b2 = gw & (1u<<(cp+8));
            bool b3 = gw & (1u<<(cp+9));

            float p0 = b0 ? ex2a(fmaf(c0[0], C1, nls0)) : 0.f;
            float p1 = b1 ? ex2a(fmaf(c0[1], C1, nls0)) : 0.f;
            float p2 = b0 ? ex2a(fmaf(c0[2], C1, nls1)) : 0.f;
            float p3 = b1 ? ex2a(fmaf(c0[3], C1, nls1)) : 0.f;
            float p4 = b2 ? ex2a(fmaf(c1[0], C1, nls0)) : 0.f;
            float p5 = b3 ? ex2a(fmaf(c1[1], C1, nls0)) : 0.f;
            float p6 = b2 ? ex2a(fmaf(c1[2], C1, nls1)) : 0.f;
            float p7 = b3 ? ex2a(fmaf(c1[3], C1, nls1)) : 0.f;

            if (write_attn) {
                int cb = kt*TK + pj*16 + cp;
                *(float2*)&Arow0[cb]     = make_float2(p0, p1);
                *(float2*)&Arow1[cb]     = make_float2(p2, p3);
                *(float2*)&Arow0[cb + 8] = make_float2(p4, p5);
                *(float2*)&Arow1[cb + 8] = make_float2(p6, p7);
            }

            uint32_t ah[4];
            ah[0] = h2bits(__floats2half2_rn(p0, p1));
            ah[1] = h2bits(__floats2half2_rn(p2, p3));
            ah[2] = h2bits(__floats2half2_rn(p4, p5));
            ah[3] = h2bits(__floats2half2_rn(p6, p7));

            uint32_t va[4], vb2[4];
            LDMX4(va,  vbase + (2*pj)*PSV + voff);
            LDMX4(vb2, vbase + (2*pj)*PSV + voff + 256);

            mma_f16(o[0], ah, va);
            mma_f16(o[1], ah, va + 2);
            mma_f16(o[2], ah, vb2);
            mma_f16(o[3], ah, vb2 + 2);
        }
        if (++stg_rd == 3) stg_rd = 0;
    }

    float* Og0 = g_O + (size_t)(nh*L_S + qr0 + wr + gid)*D_H;
    float* Og1 = g_O + (size_t)(nh*L_S + qr0 + wr + gid + 8)*D_H;
    #pragma unroll
    for (int jd = 0; jd < 4; jd++) {
        int col = jd*8 + cp;
        *(float2*)&Og0[col] = make_float2(o[jd][0], o[jd][1]);
        *(float2*)&Og1[col] = make_float2(o[jd][2], o[jd][3]);
    }
}

/* ------- kernel 4: out = concat(O) @ Wo^T + bo (register-tiled) ------- */
#define OP_PITCH 132
__global__ __launch_bounds__(256) void outproj_kernel(const float* __restrict__ Wo,
                                                      const float* __restrict__ bo,
                                                      float* __restrict__ out)
{
    __shared__ float Xs[64*OP_PITCH];
    __shared__ float Wsm[64*OP_PITCH];
    int t = threadIdx.x;
    int row0 = blockIdx.x * 64;
    int eg = t & 7;
    int rt = t >> 3;

    for (int idx = t; idx < 64*32; idx += 256) {
        int r = idx >> 5, c4 = idx & 31;
        int row = row0 + r;
        int n = row >> 12, l = row & 4095;
        int f0 = c4*4;
        float4 v = make_float4(
            g_O[(((size_t)n*H_N + (f0>>5))*L_S + l)*D_H + (f0 & 31)],
            g_O[(((size_t)n*H_N + ((f0+1)>>5))*L_S + l)*D_H + ((f0+1) & 31)],
            g_O[(((size_t)n*H_N + ((f0+2)>>5))*L_S + l)*D_H + ((f0+2) & 31)],
            g_O[(((size_t)n*H_N + ((f0+3)>>5))*L_S + l)*D_H + ((f0+3) & 31)]);
        *(float4*)&Xs[r*OP_PITCH + f0] = v;
    }

    for (int et = 0; et < 2; et++) {
        __syncthreads();
        for (int idx = t; idx < 64*32; idx += 256) {
            int e = idx >> 5, c4 = idx & 31;
            *(float4*)&Wsm[e*OP_PITCH + c4*4] =
                *(const float4*)&Wo[(size_t)(et*64 + e)*EMB + c4*4];
        }
        __syncthreads();

        float acc[2][8];
        #pragma unroll
        for (int r = 0; r < 2; r++)
            #pragma unroll
            for (int j = 0; j < 8; j++) acc[r][j] = 0.f;

        const float* x0 = &Xs[(rt*2)*OP_PITCH];
        const float* x1 = &Xs[(rt*2+1)*OP_PITCH];
        #pragma unroll 4
        for (int f = 0; f < EMB; f++) {
            float a0 = x0[f], a1 = x1[f];
            #pragma unroll
            for (int j = 0; j < 8; j++) {
                float wv = Wsm[(j*8 + eg)*OP_PITCH + f];
                acc[0][j] += a0 * wv;
                acc[1][j] += a1 * wv;
            }
        }

        #pragma unroll
        for (int r = 0; r < 2; r++) {
            int row = row0 + rt*2 + r;
            #pragma unroll
            for (int j = 0; j < 8; j++) {
                int e = et*64 + j*8 + eg;
                out[(size_t)row*EMB + e] = acc[r][j] + bo[e];
            }
        }
    }
}

/* ---------------- launch ---------------- */
extern "C" void kernel_launch(void* const* d_in, const int* in_sizes, int n_in,
                              void* d_out, int out_size)
{
    const float* values = (const float*)d_in[0];
    const float* keys   = (const float*)d_in[1];
    const float* query  = (const float*)d_in[2];
    const int*   mask   = (const int*)d_in[3];
    const float* Wv     = (const float*)d_in[4];
    const float* Wk     = (const float*)d_in[5];
    const float* Wq     = (const float*)d_in[6];
    const float* Wo     = (const float*)d_in[7];
    const float* bo     = (const float*)d_in[8];
    float* out = (float*)d_out;

    const long long out_elems  = (long long)N_B * L_S * EMB;
    const long long attn_elems = (long long)N_B * H_N * L_S * L_S;
    int has_attn = ((long long)out_size >= out_elems + attn_elems);
    float* attn_out = has_attn ? (out + out_elems) : (float*)0;

    cudaFuncSetAttribute(stats_kernel, cudaFuncAttributeMaxDynamicSharedMemorySize, SMEM_STATS);
    cudaFuncSetAttribute(attn_kernel,  cudaFuncAttributeMaxDynamicSharedMemorySize, SMEM_ATTN);

    dim3 gc(NKT, NH);
    projconv_kernel<<<gc, 256>>>(values, keys, query, Wv, Wk, Wq);

    dim3 g(L_S/TM, NH);
    stats_kernel<<<g, 256, SMEM_STATS>>>(mask);
    attn_kernel<<<g, 256, SMEM_ATTN>>>(mask, attn_out, has_attn);

    outproj_kernel<<<(N_B*L_S)/64, 256>>>(Wo, bo, out);
}

// round 12
// speedup vs baseline: 4.9603x; 1.0328x over previous
#include <cuda_runtime.h>
#include <cuda_fp16.h>
#include <math.h>
#include <stdint.h>

#define N_B 4
#define L_S 4096
#define EMB 128
#define H_N 4
#define D_H 32
#define C1 0.12751744766f       /* (1/sqrt(128)) * log2(e) */

#define TM 128
#define TK 128
#define NKT (L_S/TK)
#define NH (N_B*H_N)

#define PSQ 2048               /* QK image: 4 d-octet planes of [128 rows][16B] */
#define PSV 512                /* V image: 16 key-octet planes of [32 d][16B]   */
#define TILE_U4 512            /* 8192 bytes per tile image */

/* fused kernel smem: 3 stages x (Kh 8K + Vt 8K) + Q (8K) + maskbits */
#define F_STGSZ 16384
#define F_Q   (3*F_STGSZ)
#define F_MW  (F_Q + 8192)
#define SMEM_FUSED (F_MW + 512)

/* ---------------- scratch ---------------- */
__device__ float g_O[NH*L_S*D_H];
__device__ uint4 g_imgQh[NH*NKT*TILE_U4];
__device__ uint4 g_imgKh[NH*NKT*TILE_U4];
__device__ uint4 g_imgVt[NH*NKT*TILE_U4];

/* ---------------- helpers ---------------- */
__device__ __forceinline__ uint32_t smem_u32(const void* p){
    uint32_t a;
    asm("{ .reg .u64 t; cvta.to.shared.u64 t, %1; cvt.u32.u64 %0, t; }" : "=r"(a) : "l"(p));
    return a;
}
__device__ __forceinline__ void mma_f16(float* c, const uint32_t* a, const uint32_t* b){
    asm volatile("mma.sync.aligned.m16n8k16.row.col.f32.f16.f16.f32 "
        "{%0,%1,%2,%3}, {%4,%5,%6,%7}, {%8,%9}, {%0,%1,%2,%3};"
        : "+f"(c[0]), "+f"(c[1]), "+f"(c[2]), "+f"(c[3])
        : "r"(a[0]), "r"(a[1]), "r"(a[2]), "r"(a[3]), "r"(b[0]), "r"(b[1]));
}
#define LDMX4(r, a) \
    asm volatile("ldmatrix.sync.aligned.m8n8.x4.shared.b16 {%0,%1,%2,%3}, [%4];" \
        : "=r"((r)[0]), "=r"((r)[1]), "=r"((r)[2]), "=r"((r)[3]) : "r"(a))
#define CPA16(dst, src) \
    asm volatile("cp.async.cg.shared.global [%0], [%1], 16;" :: "r"(dst), "l"(src))
#define CPA_COMMIT() asm volatile("cp.async.commit_group;" ::: "memory")
#define CPA_WAIT(n)  asm volatile("cp.async.wait_group %0;" :: "n"(n) : "memory")

__device__ __forceinline__ float ex2a(float x){
    float r;
    asm("ex2.approx.f32 %0, %1;" : "=f"(r) : "f"(x));
    return r;
}
__device__ __forceinline__ uint32_t h2bits(__half2 v){
    return *reinterpret_cast<uint32_t*>(&v);
}

__device__ __forceinline__ void q_frags(uint32_t base, int wr, int lane, uint32_t qf[2][4])
{
    int m = lane >> 3;
    int row = wr + (m & 1)*8 + (lane & 7);
    uint32_t a0 = base + (m >> 1)*PSQ + row*16;
    LDMX4(qf[0], a0);
    LDMX4(qf[1], a0 + 2*PSQ);
}

/* ------- kernel 1: fused projection + fp16 image build ------- */
__global__ __launch_bounds__(256) void projconv_kernel(
    const float* __restrict__ vin, const float* __restrict__ kin,
    const float* __restrict__ qin,
    const float* __restrict__ Wv, const float* __restrict__ Wk,
    const float* __restrict__ Wq)
{
    __shared__ float Ws[3][D_H*33];
    __shared__ float Xs[128*33];
    int t = threadIdx.x;
    int kt = blockIdx.x, nh = blockIdx.y;
    int n = nh >> 2, h = nh & 3;
    size_t inbase = ((size_t)n*L_S + (size_t)kt*128)*EMB + h*D_H;
    size_t ti = (size_t)(nh*NKT + kt) * TILE_U4;

    for (int i = t; i < D_H*D_H; i += 256) {
        int e = i >> 5, d = i & 31;
        Ws[0][e*33+d] = Wq[i]; Ws[1][e*33+d] = Wk[i]; Ws[2][e*33+d] = Wv[i];
    }

    const float* ins[3] = { qin, kin, vin };
    uint4* qkdst[2] = { g_imgQh + ti, g_imgKh + ti };

    int r = t & 127, half = t >> 7;
    int e0 = half*16;

    for (int mm = 0; mm < 3; mm++) {
        __syncthreads();
        for (int idx = t; idx < 128*8; idx += 256) {
            int rr = idx >> 3, c4 = idx & 7;
            float4 x = *(const float4*)&ins[mm][inbase + (size_t)rr*EMB + c4*4];
            float* drow = &Xs[rr*33 + c4*4];
            drow[0] = x.x; drow[1] = x.y; drow[2] = x.z; drow[3] = x.w;
        }
        __syncthreads();

        float x[D_H];
        #pragma unroll
        for (int d = 0; d < D_H; d++) x[d] = Xs[r*33 + d];

        float o[16];
        #pragma unroll
        for (int j = 0; j < 16; j++) {
            float a = 0.f;
            const float* wrow = &Ws[mm][(e0+j)*33];
            #pragma unroll
            for (int d = 0; d < D_H; d++) a = fmaf(x[d], wrow[d], a);
            o[j] = a;
        }

        uint32_t hw[8];
        #pragma unroll
        for (int j = 0; j < 8; j++)
            hw[j] = h2bits(__floats2half2_rn(o[2*j], o[2*j+1]));

        if (mm < 2) {
            int oct0 = half*2;
            qkdst[mm][(oct0  )*128 + r] = make_uint4(hw[0], hw[1], hw[2], hw[3]);
            qkdst[mm][(oct0+1)*128 + r] = make_uint4(hw[4], hw[5], hw[6], hw[7]);
        } else {
            __syncthreads();
            float* drow = &Xs[r*33 + e0];
            #pragma unroll
            for (int j = 0; j < 16; j++) drow[j] = o[j];
            __syncthreads();
            #pragma unroll
            for (int i = 0; i < 2; i++) {
                int item = t + i*256;
                int oct = item >> 5, d = item & 31;
                uint32_t w[4];
                #pragma unroll
                for (int w2 = 0; w2 < 4; w2++) {
                    float x0 = Xs[(oct*8 + w2*2)*33 + d];
                    float x1 = Xs[(oct*8 + w2*2 + 1)*33 + d];
                    w[w2] = h2bits(__floats2half2_rn(x0, x1));
                }
                g_imgVt[ti + item] = make_uint4(w[0], w[1], w[2], w[3]);
            }
        }
    }
}

/* ------- kernel 2: fused rowsum + attn_w + O = P @ V ------- */
__global__ __launch_bounds__(256, 3) void fused_kernel(const int* __restrict__ mask,
                                                       float* __restrict__ attn_out,
                                                       int write_attn)
{
    extern __shared__ char smem[];
    uint32_t sb = smem_u32(smem);
    int t = threadIdx.x, lane = t & 31, w = t >> 5;
    int gid = lane >> 2, cp = (lane & 3)*2, wr = w*16;
    int nh = blockIdx.y, n = nh >> 2, qt = blockIdx.x, qr0 = qt * TM;
    const int* mrow = mask + n*L_S;
    uint32_t* mw = (uint32_t*)(smem + F_MW);
    float* Ag = attn_out ? attn_out + (size_t)nh*L_S*L_S : (float*)0;

    const uint4* Qh = g_imgQh + (size_t)(nh*NKT + qt)*TILE_U4;
    const uint4* Kh = g_imgKh + (size_t)nh*NKT*TILE_U4;
    const uint4* Vt = g_imgVt + (size_t)nh*NKT*TILE_U4;

    int kq = lane >> 3;
    uint32_t koff = kq*PSQ + (lane&7)*16;
    uint32_t voff = (kq & 1)*PSV + ((kq >> 1)*8 + (lane&7))*16;

    /* ---- prologue: Q (dedicated area) + stage0 K ---- */
    #pragma unroll
    for (int i = 0; i < 2; i++) {
        int it2 = t + i*256;
        CPA16(sb + F_Q + it2*16, Qh + it2);
        CPA16(sb +       it2*16, Kh + it2);
    }
    CPA_COMMIT();
    if (t < 128) {
        uint32_t wbits = 0;
        const int* mp = mrow + t*32;
        #pragma unroll 8
        for (int j = 0; j < 32; j++) wbits |= (mp[j] ? 1u : 0u) << j;
        mw[t] = wbits;
    }
    CPA_WAIT(0);
    __syncthreads();

    uint32_t qh[2][4];
    q_frags(sb + F_Q, wr, lane, qh);

    /* ---- phase 1: row sums (K-only pipeline) ---- */
    float sum0 = 0.f, sum1 = 0.f;
    int stg_rd = 0;

    for (int kt = 0; kt < NKT; kt++) {
        if (kt + 1 < NKT) {
            int stw = stg_rd + 1; if (stw == 3) stw = 0;
            uint32_t st = sb + stw*F_STGSZ;
            const uint4* src = Kh + (size_t)(kt+1)*TILE_U4;
            CPA16(st + t*16, src + t);
            CPA16(st + (t+256)*16, src + t + 256);
        }
        CPA_COMMIT();
        CPA_WAIT(1);
        __syncthreads();

        uint32_t kb = sb + stg_rd*F_STGSZ + koff;

        #pragma unroll 2
        for (int pj = 0; pj < 8; pj++) {
            uint32_t k0[4], k1[4];
            LDMX4(k0, kb + (pj*2)*128);
            LDMX4(k1, kb + (pj*2+1)*128);
            float c0[4] = {0.f,0.f,0.f,0.f};
            float c1[4] = {0.f,0.f,0.f,0.f};
            mma_f16(c0, qh[0], k0);
            mma_f16(c1, qh[0], k1);
            mma_f16(c0, qh[1], k0 + 2);
            mma_f16(c1, qh[1], k1 + 2);

            uint32_t gw = mw[(kt<<2) + (pj>>1)] >> ((pj&1)<<4);
            bool b0 = gw & (1u<<cp);
            bool b1 = gw & (1u<<(cp+1));
            bool b2 = gw & (1u<<(cp+8));
            bool b3 = gw & (1u<<(cp+9));
            float e0 = ex2a(c0[0]*C1), e1 = ex2a(c0[1]*C1);
            float e2 = ex2a(c0[2]*C1), e3 = ex2a(c0[3]*C1);
            float e4 = ex2a(c1[0]*C1), e5 = ex2a(c1[1]*C1);
            float e6 = ex2a(c1[2]*C1), e7 = ex2a(c1[3]*C1);
            sum0 += (b0 ? e0 : 0.f) + (b1 ? e1 : 0.f) + (b2 ? e4 : 0.f) + (b3 ? e5 : 0.f);
            sum1 += (b0 ? e2 : 0.f) + (b1 ? e3 : 0.f) + (b2 ? e6 : 0.f) + (b3 ? e7 : 0.f);
        }
        if (++stg_rd == 3) stg_rd = 0;
        __syncthreads();
    }
    CPA_WAIT(0);

    sum0 += __shfl_xor_sync(0xffffffffu, sum0, 1);
    sum0 += __shfl_xor_sync(0xffffffffu, sum0, 2);
    sum1 += __shfl_xor_sync(0xffffffffu, sum1, 1);
    sum1 += __shfl_xor_sync(0xffffffffu, sum1, 2);
    float nls0 = -__log2f(sum0);
    float nls1 = -__log2f(sum1);
    __syncthreads();

    /* ---- phase 2: recompute S, write attn_w, P@V ---- */
    #pragma unroll
    for (int i = 0; i < 2; i++) {
        int it2 = t + i*256;
        CPA16(sb +        it2*16, Kh + it2);
        CPA16(sb + 8192 + it2*16, Vt + it2);
    }
    CPA_COMMIT();

    float o[4][4];
    #pragma unroll
    for (int jd = 0; jd < 4; jd++)
        #pragma unroll
        for (int i = 0; i < 4; i++) o[jd][i] = 0.f;

    float* Arow0 = Ag ? Ag + (size_t)(qr0 + wr + gid)*L_S : (float*)0;
    float* Arow1 = Ag ? Ag + (size_t)(qr0 + wr + gid + 8)*L_S : (float*)0;

    stg_rd = 0;
    for (int kt = 0; kt < NKT; kt++) {
        if (kt + 1 < NKT) {
            int stw = stg_rd + 1; if (stw == 3) stw = 0;
            uint32_t st = sb + stw*F_STGSZ;
            size_t ti = (size_t)(kt+1)*TILE_U4;
            #pragma unroll
            for (int i = 0; i < 2; i++) {
                int it2 = t + i*256;
                CPA16(st + it2*16,        Kh + ti + it2);
                CPA16(st + 8192 + it2*16, Vt + ti + it2);
            }
        }
        CPA_COMMIT();
        CPA_WAIT(1);
        __syncthreads();

        uint32_t stg = sb + stg_rd*F_STGSZ;
        uint32_t kbh = stg + koff;
        uint32_t vbase = stg + 8192;

        #pragma unroll 1
        for (int pj = 0; pj < 8; pj++) {
            uint32_t k0[4], k1[4];
            LDMX4(k0, kbh + (pj*2)*128);
            LDMX4(k1, kbh + (pj*2+1)*128);

            float c0[4] = {0.f,0.f,0.f,0.f};
            float c1[4] = {0.f,0.f,0.f,0.f};
            mma_f16(c0, qh[0], k0);
            mma_f16(c1, qh[0], k1);
            mma_f16(c0, qh[1], k0 + 2);
            mma_f16(c1, qh[1], k1 + 2);

            uint32_t gw = mw[(kt<<2) + (pj>>1)] >> ((pj&1)<<4);
            bool b0 = gw & (1u<<cp);
            bool b1 = gw & (1u<<(cp+1));
            bool b2 = gw & (1u<<(cp+8));
            bool b3 = gw & (1u<<(cp+9));

            float p0 = b0 ? ex2a(fmaf(c0[0], C1, nls0)) : 0.f;
            float p1 = b1 ? ex2a(fmaf(c0[1], C1, nls0)) : 0.f;
            float p2 = b0 ? ex2a(fmaf(c0[2], C1, nls1)) : 0.f;
            float p3 = b1 ? ex2a(fmaf(c0[3], C1, nls1)) : 0.f;
            float p4 = b2 ? ex2a(fmaf(c1[0], C1, nls0)) : 0.f;
            float p5 = b3 ? ex2a(fmaf(c1[1], C1, nls0)) : 0.f;
            float p6 = b2 ? ex2a(fmaf(c1[2], C1, nls1)) : 0.f;
            float p7 = b3 ? ex2a(fmaf(c1[3], C1, nls1)) : 0.f;

            if (write_attn) {
                int cb = kt*TK + pj*16 + cp;
                *(float2*)&Arow0[cb]     = make_float2(p0, p1);
                *(float2*)&Arow1[cb]     = make_float2(p2, p3);
                *(float2*)&Arow0[cb + 8] = make_float2(p4, p5);
                *(float2*)&Arow1[cb + 8] = make_float2(p6, p7);
            }

            uint32_t ah[4];
            ah[0] = h2bits(__floats2half2_rn(p0, p1));
            ah[1] = h2bits(__floats2half2_rn(p2, p3));
            ah[2] = h2bits(__floats2half2_rn(p4, p5));
            ah[3] = h2bits(__floats2half2_rn(p6, p7));

            uint32_t va[4], vb2[4];
            LDMX4(va,  vbase + (2*pj)*PSV + voff);
            LDMX4(vb2, vbase + (2*pj)*PSV + voff + 256);

            mma_f16(o[0], ah, va);
            mma_f16(o[1], ah, va + 2);
            mma_f16(o[2], ah, vb2);
            mma_f16(o[3], ah, vb2 + 2);
        }
        if (++stg_rd == 3) stg_rd = 0;
        __syncthreads();
    }

    float* Og0 = g_O + (size_t)(nh*L_S + qr0 + wr + gid)*D_H;
    float* Og1 = g_O + (size_t)(nh*L_S + qr0 + wr + gid + 8)*D_H;
    #pragma unroll
    for (int jd = 0; jd < 4; jd++) {
        int col = jd*8 + cp;
        *(float2*)&Og0[col] = make_float2(o[jd][0], o[jd][1]);
        *(float2*)&Og1[col] = make_float2(o[jd][2], o[jd][3]);
    }
}

/* ------- kernel 3: out = concat(O) @ Wo^T + bo (register-tiled) ------- */
#define OP_PITCH 132
__global__ __launch_bounds__(256) void outproj_kernel(const float* __restrict__ Wo,
                                                      const float* __restrict__ bo,
                                                      float* __restrict__ out)
{
    __shared__ float Xs[64*OP_PITCH];
    __shared__ float Wsm[64*OP_PITCH];
    int t = threadIdx.x;
    int row0 = blockIdx.x * 64;
    int eg = t & 7;
    int rt = t >> 3;

    for (int idx = t; idx < 64*32; idx += 256) {
        int r = idx >> 5, c4 = idx & 31;
        int row = row0 + r;
        int n = row >> 12, l = row & 4095;
        int f0 = c4*4;
        float4 v = make_float4(
            g_O[(((size_t)n*H_N + (f0>>5))*L_S + l)*D_H + (f0 & 31)],
            g_O[(((size_t)n*H_N + ((f0+1)>>5))*L_S + l)*D_H + ((f0+1) & 31)],
            g_O[(((size_t)n*H_N + ((f0+2)>>5))*L_S + l)*D_H + ((f0+2) & 31)],
            g_O[(((size_t)n*H_N + ((f0+3)>>5))*L_S + l)*D_H + ((f0+3) & 31)]);
        *(float4*)&Xs[r*OP_PITCH + f0] = v;
    }

    for (int et = 0; et < 2; et++) {
        __syncthreads();
        for (int idx = t; idx < 64*32; idx += 256) {
            int e = idx >> 5, c4 = idx & 31;
            *(float4*)&Wsm[e*OP_PITCH + c4*4] =
                *(const float4*)&Wo[(size_t)(et*64 + e)*EMB + c4*4];
        }
        __syncthreads();

        float acc[2][8];
        #pragma unroll
        for (int r = 0; r < 2; r++)
            #pragma unroll
            for (int j = 0; j < 8; j++) acc[r][j] = 0.f;

        const float* x0 = &Xs[(rt*2)*OP_PITCH];
        const float* x1 = &Xs[(rt*2+1)*OP_PITCH];
        #pragma unroll 4
        for (int f = 0; f < EMB; f++) {
            float a0 = x0[f], a1 = x1[f];
            #pragma unroll
            for (int j = 0; j < 8; j++) {
                float wv = Wsm[(j*8 + eg)*OP_PITCH + f];
                acc[0][j] += a0 * wv;
                acc[1][j] += a1 * wv;
            }
        }

        #pragma unroll
        for (int r = 0; r < 2; r++) {
            int row = row0 + rt*2 + r;
            #pragma unroll
            for (int j = 0; j < 8; j++) {
                int e = et*64 + j*8 + eg;
                out[(size_t)row*EMB + e] = acc[r][j] + bo[e];
            }
        }
    }
}

/* ---------------- launch ---------------- */
extern "C" void kernel_launch(void* const* d_in, const int* in_sizes, int n_in,
                              void* d_out, int out_size)
{
    const float* values = (const float*)d_in[0];
    const float* keys   = (const float*)d_in[1];
    const float* query  = (const float*)d_in[2];
    const int*   mask   = (const int*)d_in[3];
    const float* Wv     = (const float*)d_in[4];
    const float* Wk     = (const float*)d_in[5];
    const float* Wq     = (const float*)d_in[6];
    const float* Wo     = (const float*)d_in[7];
    const float* bo     = (const float*)d_in[8];
    float* out = (float*)d_out;

    const long long out_elems  = (long long)N_B * L_S * EMB;
    const long long attn_elems = (long long)N_B * H_N * L_S * L_S;
    int has_attn = ((long long)out_size >= out_elems + attn_elems);
    float* attn_out = has_attn ? (out + out_elems) : (float*)0;

    cudaFuncSetAttribute(fused_kernel, cudaFuncAttributeMaxDynamicSharedMemorySize, SMEM_FUSED);

    dim3 gc(NKT, NH);
    projconv_kernel<<<gc, 256>>>(values, keys, query, Wv, Wk, Wq);

    dim3 g(L_S/TM, NH);
    fused_kernel<<<g, 256, SMEM_FUSED>>>(mask, attn_out, has_attn);

    outproj_kernel<<<(N_B*L_S)/64, 256>>>(Wo, bo, out);
}

// round 13
// speedup vs baseline: 5.0971x; 1.0276x over previous
#include <cuda_runtime.h>
#include <cuda_fp16.h>
#include <math.h>
#include <stdint.h>

#define N_B 4
#define L_S 4096
#define EMB 128
#define H_N 4
#define D_H 32
#define C1 0.12751744766f       /* (1/sqrt(128)) * log2(e) */
#define MASKF (-3.0e38f)

#define TM 128
#define TK 128
#define NKT (L_S/TK)
#define NH (N_B*H_N)

#define PSQ 2048               /* QK image: 4 d-octet planes of [128 rows][16B] */
#define PSV 512                /* V image: 16 key-octet planes of [32 d][16B]   */
#define TILE_U4 512            /* 8192 bytes per tile image */

/* fused kernel smem: 3 stages x (Kh 8K + Vt 8K) + Q (8K) + fp32 bias (16K) */
#define F_STGSZ 16384
#define F_Q    (3*F_STGSZ)
#define F_BIAS (F_Q + 8192)
#define SMEM_FUSED (F_BIAS + 16384)

/* ---------------- scratch ---------------- */
__device__ float g_O[NH*L_S*D_H];
__device__ uint4 g_imgQh[NH*NKT*TILE_U4];
__device__ uint4 g_imgKh[NH*NKT*TILE_U4];
__device__ uint4 g_imgVt[NH*NKT*TILE_U4];

/* ---------------- helpers ---------------- */
__device__ __forceinline__ uint32_t smem_u32(const void* p){
    uint32_t a;
    asm("{ .reg .u64 t; cvta.to.shared.u64 t, %1; cvt.u32.u64 %0, t; }" : "=r"(a) : "l"(p));
    return a;
}
__device__ __forceinline__ void mma_f16(float* c, const uint32_t* a, const uint32_t* b){
    asm volatile("mma.sync.aligned.m16n8k16.row.col.f32.f16.f16.f32 "
        "{%0,%1,%2,%3}, {%4,%5,%6,%7}, {%8,%9}, {%0,%1,%2,%3};"
        : "+f"(c[0]), "+f"(c[1]), "+f"(c[2]), "+f"(c[3])
        : "r"(a[0]), "r"(a[1]), "r"(a[2]), "r"(a[3]), "r"(b[0]), "r"(b[1]));
}
#define LDMX4(r, a) \
    asm volatile("ldmatrix.sync.aligned.m8n8.x4.shared.b16 {%0,%1,%2,%3}, [%4];" \
        : "=r"((r)[0]), "=r"((r)[1]), "=r"((r)[2]), "=r"((r)[3]) : "r"(a))
#define CPA16(dst, src) \
    asm volatile("cp.async.cg.shared.global [%0], [%1], 16;" :: "r"(dst), "l"(src))
#define CPA_COMMIT() asm volatile("cp.async.commit_group;" ::: "memory")
#define CPA_WAIT(n)  asm volatile("cp.async.wait_group %0;" :: "n"(n) : "memory")

__device__ __forceinline__ float ex2a(float x){
    float r;
    asm("ex2.approx.f32 %0, %1;" : "=f"(r) : "f"(x));
    return r;
}
__device__ __forceinline__ uint32_t h2bits(__half2 v){
    return *reinterpret_cast<uint32_t*>(&v);
}

__device__ __forceinline__ void q_frags(uint32_t base, int wr, int lane, uint32_t qf[2][4])
{
    int m = lane >> 3;
    int row = wr + (m & 1)*8 + (lane & 7);
    uint32_t a0 = base + (m >> 1)*PSQ + row*16;
    LDMX4(qf[0], a0);
    LDMX4(qf[1], a0 + 2*PSQ);
}

/* ------- kernel 1: fused projection + fp16 image build ------- */
/* grid (NKT, NH, 3): z selects Q / K / V */
__global__ __launch_bounds__(256) void projconv_kernel(
    const float* __restrict__ vin, const float* __restrict__ kin,
    const float* __restrict__ qin,
    const float* __restrict__ Wv, const float* __restrict__ Wk,
    const float* __restrict__ Wq)
{
    __shared__ float Ws[D_H*33];
    __shared__ float Xs[128*33];
    int t = threadIdx.x;
    int kt = blockIdx.x, nh = blockIdx.y, mm = blockIdx.z;
    int n = nh >> 2, h = nh & 3;
    size_t inbase = ((size_t)n*L_S + (size_t)kt*128)*EMB + h*D_H;
    size_t ti = (size_t)(nh*NKT + kt) * TILE_U4;

    const float* in = (mm == 0) ? qin : (mm == 1 ? kin : vin);
    const float* W  = (mm == 0) ? Wq  : (mm == 1 ? Wk  : Wv);

    for (int i = t; i < D_H*D_H; i += 256) {
        int e = i >> 5, d = i & 31;
        Ws[e*33+d] = W[i];
    }
    for (int idx = t; idx < 128*8; idx += 256) {
        int rr = idx >> 3, c4 = idx & 7;
        float4 x = *(const float4*)&in[inbase + (size_t)rr*EMB + c4*4];
        float* drow = &Xs[rr*33 + c4*4];
        drow[0] = x.x; drow[1] = x.y; drow[2] = x.z; drow[3] = x.w;
    }
    __syncthreads();

    int r = t & 127, half = t >> 7;
    int e0 = half*16;

    float x[D_H];
    #pragma unroll
    for (int d = 0; d < D_H; d++) x[d] = Xs[r*33 + d];

    float o[16];
    #pragma unroll
    for (int j = 0; j < 16; j++) {
        float a = 0.f;
        const float* wrow = &Ws[(e0+j)*33];
        #pragma unroll
        for (int d = 0; d < D_H; d++) a = fmaf(x[d], wrow[d], a);
        o[j] = a;
    }

    if (mm < 2) {
        uint32_t hw[8];
        #pragma unroll
        for (int j = 0; j < 8; j++)
            hw[j] = h2bits(__floats2half2_rn(o[2*j], o[2*j+1]));
        uint4* dst = (mm == 0 ? g_imgQh : g_imgKh) + ti;
        int oct0 = half*2;
        dst[(oct0  )*128 + r] = make_uint4(hw[0], hw[1], hw[2], hw[3]);
        dst[(oct0+1)*128 + r] = make_uint4(hw[4], hw[5], hw[6], hw[7]);
    } else {
        __syncthreads();      /* everyone's x regs loaded before overwrite */
        float* drow = &Xs[r*33 + e0];
        #pragma unroll
        for (int j = 0; j < 16; j++) drow[j] = o[j];
        __syncthreads();
        #pragma unroll
        for (int i = 0; i < 2; i++) {
            int item = t + i*256;
            int oct = item >> 5, d = item & 31;
            uint32_t w2v[4];
            #pragma unroll
            for (int w2 = 0; w2 < 4; w2++) {
                float x0 = Xs[(oct*8 + w2*2)*33 + d];
                float x1 = Xs[(oct*8 + w2*2 + 1)*33 + d];
                w2v[w2] = h2bits(__floats2half2_rn(x0, x1));
            }
            g_imgVt[ti + item] = make_uint4(w2v[0], w2v[1], w2v[2], w2v[3]);
        }
    }
}

/* ------- kernel 2: fused rowsum + attn_w + O = P @ V ------- */
__global__ __launch_bounds__(256, 3) void fused_kernel(const int* __restrict__ mask,
                                                       float* __restrict__ attn_out,
                                                       int write_attn)
{
    extern __shared__ char smem[];
    uint32_t sb = smem_u32(smem);
    int t = threadIdx.x, lane = t & 31, w = t >> 5;
    int gid = lane >> 2, cp = (lane & 3)*2, wr = w*16;
    int nh = blockIdx.y, n = nh >> 2, qt = blockIdx.x, qr0 = qt * TM;
    const int* mrow = mask + n*L_S;
    float* bias = (float*)(smem + F_BIAS);
    float* Ag = attn_out ? attn_out + (size_t)nh*L_S*L_S : (float*)0;

    const uint4* Qh = g_imgQh + (size_t)(nh*NKT + qt)*TILE_U4;
    const uint4* Kh = g_imgKh + (size_t)nh*NKT*TILE_U4;
    const uint4* Vt = g_imgVt + (size_t)nh*NKT*TILE_U4;

    int kq = lane >> 3;
    uint32_t koff = kq*PSQ + (lane&7)*16;
    uint32_t voff = (kq & 1)*PSV + ((kq >> 1)*8 + (lane&7))*16;

    /* ---- prologue: Q + stage0 K; bias build ---- */
    #pragma unroll
    for (int i = 0; i < 2; i++) {
        int it2 = t + i*256;
        CPA16(sb + F_Q + it2*16, Qh + it2);
        CPA16(sb +       it2*16, Kh + it2);
    }
    CPA_COMMIT();
    #pragma unroll
    for (int i = 0; i < 16; i++) {
        int idx = t + i*256;
        bias[idx] = mrow[idx] ? 0.f : MASKF;
    }
    CPA_WAIT(0);
    __syncthreads();

    uint32_t qh[2][4];
    q_frags(sb + F_Q, wr, lane, qh);

    /* ---- phase 1: row sums (K-only 3-stage ring) ---- */
    float sum0 = 0.f, sum1 = 0.f;
    int stg_rd = 0;

    for (int kt = 0; kt < NKT; kt++) {
        if (kt + 1 < NKT) {
            int stw = stg_rd + 1; if (stw == 3) stw = 0;
            uint32_t st = sb + stw*F_STGSZ;
            const uint4* src = Kh + (size_t)(kt+1)*TILE_U4;
            CPA16(st + t*16, src + t);
            CPA16(st + (t+256)*16, src + t + 256);
        }
        CPA_COMMIT();
        CPA_WAIT(1);
        __syncthreads();

        uint32_t kb = sb + stg_rd*F_STGSZ + koff;
        const float* bk = bias + kt*TK;

        #pragma unroll 4
        for (int pj = 0; pj < 8; pj++) {
            uint32_t k0[4], k1[4];
            LDMX4(k0, kb + (pj*2)*128);
            LDMX4(k1, kb + (pj*2+1)*128);
            float c0[4] = {0.f,0.f,0.f,0.f};
            float c1[4] = {0.f,0.f,0.f,0.f};
            mma_f16(c0, qh[0], k0);
            mma_f16(c1, qh[0], k1);
            mma_f16(c0, qh[1], k0 + 2);
            mma_f16(c1, qh[1], k1 + 2);

            float2 ba = *(const float2*)&bk[pj*16 + cp];
            float2 bb = *(const float2*)&bk[pj*16 + 8 + cp];
            sum0 += ex2a(fmaf(c0[0], C1, ba.x)) + ex2a(fmaf(c0[1], C1, ba.y))
                  + ex2a(fmaf(c1[0], C1, bb.x)) + ex2a(fmaf(c1[1], C1, bb.y));
            sum1 += ex2a(fmaf(c0[2], C1, ba.x)) + ex2a(fmaf(c0[3], C1, ba.y))
                  + ex2a(fmaf(c1[2], C1, bb.x)) + ex2a(fmaf(c1[3], C1, bb.y));
        }
        if (++stg_rd == 3) stg_rd = 0;
    }
    __syncthreads();                 /* all phase-1 reads done before stage0 reuse */

    /* phase-2 prologue issued early, overlaps the reduction */
    #pragma unroll
    for (int i = 0; i < 2; i++) {
        int it2 = t + i*256;
        CPA16(sb +        it2*16, Kh + it2);
        CPA16(sb + 8192 + it2*16, Vt + it2);
    }
    CPA_COMMIT();

    sum0 += __shfl_xor_sync(0xffffffffu, sum0, 1);
    sum0 += __shfl_xor_sync(0xffffffffu, sum0, 2);
    sum1 += __shfl_xor_sync(0xffffffffu, sum1, 1);
    sum1 += __shfl_xor_sync(0xffffffffu, sum1, 2);
    float nls0 = -__log2f(sum0);
    float nls1 = -__log2f(sum1);

    /* ---- phase 2: recompute S, write attn_w, P@V ---- */
    float o[4][4];
    #pragma unroll
    for (int jd = 0; jd < 4; jd++)
        #pragma unroll
        for (int i = 0; i < 4; i++) o[jd][i] = 0.f;

    float* Arow0 = Ag ? Ag + (size_t)(qr0 + wr + gid)*L_S : (float*)0;
    float* Arow1 = Ag ? Ag + (size_t)(qr0 + wr + gid + 8)*L_S : (float*)0;

    stg_rd = 0;
    for (int kt = 0; kt < NKT; kt++) {
        if (kt + 1 < NKT) {
            int stw = stg_rd + 1; if (stw == 3) stw = 0;
            uint32_t st = sb + stw*F_STGSZ;
            size_t ti = (size_t)(kt+1)*TILE_U4;
            #pragma unroll
            for (int i = 0; i < 2; i++) {
                int it2 = t + i*256;
                CPA16(st + it2*16,        Kh + ti + it2);
                CPA16(st + 8192 + it2*16, Vt + ti + it2);
            }
        }
        CPA_COMMIT();
        CPA_WAIT(1);
        __syncthreads();

        uint32_t stg = sb + stg_rd*F_STGSZ;
        uint32_t kbh = stg + koff;
        uint32_t vb0 = stg + 8192 + voff;
        const float* bk = bias + kt*TK;
        float* a0 = Arow0 ? Arow0 + kt*TK + cp : (float*)0;
        float* a1 = Arow1 ? Arow1 + kt*TK + cp : (float*)0;

        #pragma unroll 4
        for (int pj = 0; pj < 8; pj++) {
            uint32_t k0[4], k1[4];
            LDMX4(k0, kbh + (pj*2)*128);
            LDMX4(k1, kbh + (pj*2+1)*128);

            float c0[4] = {0.f,0.f,0.f,0.f};
            float c1[4] = {0.f,0.f,0.f,0.f};
            mma_f16(c0, qh[0], k0);
            mma_f16(c1, qh[0], k1);
            mma_f16(c0, qh[1], k0 + 2);
            mma_f16(c1, qh[1], k1 + 2);

            float2 ba = *(const float2*)&bk[pj*16 + cp];
            float2 bb = *(const float2*)&bk[pj*16 + 8 + cp];
            float p0 = ex2a(fmaf(c0[0], C1, nls0 + ba.x));
            float p1 = ex2a(fmaf(c0[1], C1, nls0 + ba.y));
            float p2 = ex2a(fmaf(c0[2], C1, nls1 + ba.x));
            float p3 = ex2a(fmaf(c0[3], C1, nls1 + ba.y));
            float p4 = ex2a(fmaf(c1[0], C1, nls0 + bb.x));
            float p5 = ex2a(fmaf(c1[1], C1, nls0 + bb.y));
            float p6 = ex2a(fmaf(c1[2], C1, nls1 + bb.x));
            float p7 = ex2a(fmaf(c1[3], C1, nls1 + bb.y));

            if (write_attn) {
                *(float2*)&a0[pj*16]     = make_float2(p0, p1);
                *(float2*)&a1[pj*16]     = make_float2(p2, p3);
                *(float2*)&a0[pj*16 + 8] = make_float2(p4, p5);
                *(float2*)&a1[pj*16 + 8] = make_float2(p6, p7);
            }

            uint32_t ah[4];
            ah[0] = h2bits(__floats2half2_rn(p0, p1));
            ah[1] = h2bits(__floats2half2_rn(p2, p3));
            ah[2] = h2bits(__floats2half2_rn(p4, p5));
            ah[3] = h2bits(__floats2half2_rn(p6, p7));

            uint32_t va[4], vb2[4];
            LDMX4(va,  vb0 + (2*pj)*PSV);
            LDMX4(vb2, vb0 + (2*pj)*PSV + 256);

            mma_f16(o[0], ah, va);
            mma_f16(o[1], ah, va + 2);
            mma_f16(o[2], ah, vb2);
            mma_f16(o[3], ah, vb2 + 2);
        }
        if (++stg_rd == 3) stg_rd = 0;
    }

    float* Og0 = g_O + (size_t)(nh*L_S + qr0 + wr + gid)*D_H;
    float* Og1 = g_O + (size_t)(nh*L_S + qr0 + wr + gid + 8)*D_H;
    #pragma unroll
    for (int jd = 0; jd < 4; jd++) {
        int col = jd*8 + cp;
        *(float2*)&Og0[col] = make_float2(o[jd][0], o[jd][1]);
        *(float2*)&Og1[col] = make_float2(o[jd][2], o[jd][3]);
    }
}

/* ------- kernel 3: out = concat(O) @ Wo^T + bo (register-tiled) ------- */
#define OP_PITCH 132
__global__ __launch_bounds__(256) void outproj_kernel(const float* __restrict__ Wo,
                                                      const float* __restrict__ bo,
                                                      float* __restrict__ out)
{
    __shared__ float Xs[64*OP_PITCH];
    __shared__ float Wsm[64*OP_PITCH];
    int t = threadIdx.x;
    int row0 = blockIdx.x * 64;
    int eg = t & 7;
    int rt = t >> 3;

    for (int idx = t; idx < 64*32; idx += 256) {
        int r = idx >> 5, c4 = idx & 31;
        int row = row0 + r;
        int n = row >> 12, l = row & 4095;
        int f0 = c4*4;
        float4 v = make_float4(
            g_O[(((size_t)n*H_N + (f0>>5))*L_S + l)*D_H + (f0 & 31)],
            g_O[(((size_t)n*H_N + ((f0+1)>>5))*L_S + l)*D_H + ((f0+1) & 31)],
            g_O[(((size_t)n*H_N + ((f0+2)>>5))*L_S + l)*D_H + ((f0+2) & 31)],
            g_O[(((size_t)n*H_N + ((f0+3)>>5))*L_S + l)*D_H + ((f0+3) & 31)]);
        *(float4*)&Xs[r*OP_PITCH + f0] = v;
    }

    for (int et = 0; et < 2; et++) {
        __syncthreads();
        for (int idx = t; idx < 64*32; idx += 256) {
            int e = idx >> 5, c4 = idx & 31;
            *(float4*)&Wsm[e*OP_PITCH + c4*4] =
                *(const float4*)&Wo[(size_t)(et*64 + e)*EMB + c4*4];
        }
        __syncthreads();

        float acc[2][8];
        #pragma unroll
        for (int r = 0; r < 2; r++)
            #pragma unroll
            for (int j = 0; j < 8; j++) acc[r][j] = 0.f;

        const float* x0 = &Xs[(rt*2)*OP_PITCH];
        const float* x1 = &Xs[(rt*2+1)*OP_PITCH];
        #pragma unroll 4
        for (int f = 0; f < EMB; f++) {
            float a0 = x0[f], a1 = x1[f];
            #pragma unroll
            for (int j = 0; j < 8; j++) {
                float wv = Wsm[(j*8 + eg)*OP_PITCH + f];
                acc[0][j] += a0 * wv;
                acc[1][j] += a1 * wv;
            }
        }

        #pragma unroll
        for (int r = 0; r < 2; r++) {
            int row = row0 + rt*2 + r;
            #pragma unroll
            for (int j = 0; j < 8; j++) {
                int e = et*64 + j*8 + eg;
                out[(size_t)row*EMB + e] = acc[r][j] + bo[e];
            }
        }
    }
}

/* ---------------- launch ---------------- */
extern "C" void kernel_launch(void* const* d_in, const int* in_sizes, int n_in,
                              void* d_out, int out_size)
{
    const float* values = (const float*)d_in[0];
    const float* keys   = (const float*)d_in[1];
    const float* query  = (const float*)d_in[2];
    const int*   mask   = (const int*)d_in[3];
    const float* Wv     = (const float*)d_in[4];
    const float* Wk     = (const float*)d_in[5];
    const float* Wq     = (const float*)d_in[6];
    const float* Wo     = (const float*)d_in[7];
    const float* bo     = (const float*)d_in[8];
    float* out = (float*)d_out;

    const long long out_elems  = (long long)N_B * L_S * EMB;
    const long long attn_elems = (long long)N_B * H_N * L_S * L_S;
    int has_attn = ((long long)out_size >= out_elems + attn_elems);
    float* attn_out = has_attn ? (out + out_elems) : (float*)0;

    cudaFuncSetAttribute(fused_kernel, cudaFuncAttributeMaxDynamicSharedMemorySize, SMEM_FUSED);

    dim3 gc(NKT, NH, 3);
    projconv_kernel<<<gc, 256>>>(values, keys, query, Wv, Wk, Wq);

    dim3 g(L_S/TM, NH);
    fused_kernel<<<g, 256, SMEM_FUSED>>>(mask, attn_out, has_attn);

    outproj_kernel<<<(N_B*L_S)/64, 256>>>(Wo, bo, out);
}

// round 15
// speedup vs baseline: 5.2256x; 1.0252x over previous
#include <cuda_runtime.h>
#include <cuda_fp16.h>
#include <math.h>
#include <stdint.h>

#define N_B 4
#define L_S 4096
#define EMB 128
#define H_N 4
#define D_H 32
#define C1 0.12751744766f       /* (1/sqrt(128)) * log2(e) */
#define MASKF (-3.0e38f)

#define TM 128
#define TK 128
#define NKT (L_S/TK)
#define NH (N_B*H_N)

#define PSQ 2048               /* QK image: 4 d-octet planes of [128 rows][16B] */
#define PSV 512                /* V image: 16 key-octet planes of [32 d][16B]   */
#define TILE_U4 512            /* 8192 bytes per tile image */

/* fused kernel smem: 3 stages x (Kh 8K + Vt 8K) + Q (8K) + fp32 bias (16K) */
#define F_STGSZ 16384
#define F_Q    (3*F_STGSZ)
#define F_BIAS (F_Q + 8192)
#define SMEM_FUSED (F_BIAS + 16384)

/* ---------------- scratch ---------------- */
__device__ float g_O[NH*L_S*D_H];
__device__ uint4 g_imgQh[NH*NKT*TILE_U4];
__device__ uint4 g_imgKh[NH*NKT*TILE_U4];
__device__ uint4 g_imgVt[NH*NKT*TILE_U4];

/* ---------------- helpers ---------------- */
__device__ __forceinline__ uint32_t smem_u32(const void* p){
    uint32_t a;
    asm("{ .reg .u64 t; cvta.to.shared.u64 t, %1; cvt.u32.u64 %0, t; }" : "=r"(a) : "l"(p));
    return a;
}
__device__ __forceinline__ void mma_f16(float* c, const uint32_t* a, const uint32_t* b){
    asm volatile("mma.sync.aligned.m16n8k16.row.col.f32.f16.f16.f32 "
        "{%0,%1,%2,%3}, {%4,%5,%6,%7}, {%8,%9}, {%0,%1,%2,%3};"
        : "+f"(c[0]), "+f"(c[1]), "+f"(c[2]), "+f"(c[3])
        : "r"(a[0]), "r"(a[1]), "r"(a[2]), "r"(a[3]), "r"(b[0]), "r"(b[1]));
}
#define LDMX4(r, a) \
    asm volatile("ldmatrix.sync.aligned.m8n8.x4.shared.b16 {%0,%1,%2,%3}, [%4];" \
        : "=r"((r)[0]), "=r"((r)[1]), "=r"((r)[2]), "=r"((r)[3]) : "r"(a))
#define CPA16(dst, src) \
    asm volatile("cp.async.cg.shared.global [%0], [%1], 16;" :: "r"(dst), "l"(src))
#define CPA_COMMIT() asm volatile("cp.async.commit_group;" ::: "memory")
#define CPA_WAIT(n)  asm volatile("cp.async.wait_group %0;" :: "n"(n) : "memory")

__device__ __forceinline__ float ex2a(float x){
    float r;
    asm("ex2.approx.f32 %0, %1;" : "=f"(r) : "f"(x));
    return r;
}
__device__ __forceinline__ uint32_t h2bits(__half2 v){
    return *reinterpret_cast<uint32_t*>(&v);
}

__device__ __forceinline__ void q_frags(uint32_t base, int wr, int lane, uint32_t qf[2][4])
{
    int m = lane >> 3;
    int row = wr + (m & 1)*8 + (lane & 7);
    uint32_t a0 = base + (m >> 1)*PSQ + row*16;
    LDMX4(qf[0], a0);
    LDMX4(qf[1], a0 + 2*PSQ);
}

/* ------- kernel 1: fused projection + fp16 image build ------- */
/* grid (NKT, NH, 3): z selects Q / K / V */
__global__ __launch_bounds__(256) void projconv_kernel(
    const float* __restrict__ vin, const float* __restrict__ kin,
    const float* __restrict__ qin,
    const float* __restrict__ Wv, const float* __restrict__ Wk,
    const float* __restrict__ Wq)
{
    __shared__ float Ws[D_H*33];
    __shared__ float Xs[128*33];
    int t = threadIdx.x;
    int kt = blockIdx.x, nh = blockIdx.y, mm = blockIdx.z;
    int n = nh >> 2, h = nh & 3;
    size_t inbase = ((size_t)n*L_S + (size_t)kt*128)*EMB + h*D_H;
    size_t ti = (size_t)(nh*NKT + kt) * TILE_U4;

    const float* in = (mm == 0) ? qin : (mm == 1 ? kin : vin);
    const float* W  = (mm == 0) ? Wq  : (mm == 1 ? Wk  : Wv);

    for (int i = t; i < D_H*D_H; i += 256) {
        int e = i >> 5, d = i & 31;
        Ws[e*33+d] = W[i];
    }
    for (int idx = t; idx < 128*8; idx += 256) {
        int rr = idx >> 3, c4 = idx & 7;
        float4 x = *(const float4*)&in[inbase + (size_t)rr*EMB + c4*4];
        float* drow = &Xs[rr*33 + c4*4];
        drow[0] = x.x; drow[1] = x.y; drow[2] = x.z; drow[3] = x.w;
    }
    __syncthreads();

    int r = t & 127, half = t >> 7;
    int e0 = half*16;

    float x[D_H];
    #pragma unroll
    for (int d = 0; d < D_H; d++) x[d] = Xs[r*33 + d];

    float o[16];
    #pragma unroll
    for (int j = 0; j < 16; j++) {
        float a = 0.f;
        const float* wrow = &Ws[(e0+j)*33];
        #pragma unroll
        for (int d = 0; d < D_H; d++) a = fmaf(x[d], wrow[d], a);
        o[j] = a;
    }

    if (mm < 2) {
        uint32_t hw[8];
        #pragma unroll
        for (int j = 0; j < 8; j++)
            hw[j] = h2bits(__floats2half2_rn(o[2*j], o[2*j+1]));
        uint4* dst = (mm == 0 ? g_imgQh : g_imgKh) + ti;
        int oct0 = half*2;
        dst[(oct0  )*128 + r] = make_uint4(hw[0], hw[1], hw[2], hw[3]);
        dst[(oct0+1)*128 + r] = make_uint4(hw[4], hw[5], hw[6], hw[7]);
    } else {
        __syncthreads();      /* everyone's x regs loaded before overwrite */
        float* drow = &Xs[r*33 + e0];
        #pragma unroll
        for (int j = 0; j < 16; j++) drow[j] = o[j];
        __syncthreads();
        #pragma unroll
        for (int i = 0; i < 2; i++) {
            int item = t + i*256;
            int oct = item >> 5, d = item & 31;
            uint32_t w2v[4];
            #pragma unroll
            for (int w2 = 0; w2 < 4; w2++) {
                float x0 = Xs[(oct*8 + w2*2)*33 + d];
                float x1 = Xs[(oct*8 + w2*2 + 1)*33 + d];
                w2v[w2] = h2bits(__floats2half2_rn(x0, x1));
            }
            g_imgVt[ti + item] = make_uint4(w2v[0], w2v[1], w2v[2], w2v[3]);
        }
    }
}

/* ------- kernel 2: fused rowsum + attn_w + O = P @ V ------- */
__global__ __launch_bounds__(256, 3) void fused_kernel(const int* __restrict__ mask,
                                                       float* __restrict__ attn_out,
                                                       int write_attn)
{
    extern __shared__ char smem[];
    uint32_t sb = smem_u32(smem);
    int t = threadIdx.x, lane = t & 31, w = t >> 5;
    int gid = lane >> 2, cp = (lane & 3)*2, wr = w*16;
    int nh = blockIdx.y, n = nh >> 2, qt = blockIdx.x, qr0 = qt * TM;
    const int* mrow = mask + n*L_S;
    float* bias = (float*)(smem + F_BIAS);
    float* Ag = attn_out ? attn_out + (size_t)nh*L_S*L_S : (float*)0;

    const uint4* Qh = g_imgQh + (size_t)(nh*NKT + qt)*TILE_U4;
    const uint4* Kh = g_imgKh + (size_t)nh*NKT*TILE_U4;
    const uint4* Vt = g_imgVt + (size_t)nh*NKT*TILE_U4;

    int kq = lane >> 3;
    uint32_t koff = kq*PSQ + (lane&7)*16;
    uint32_t voff = (kq & 1)*PSV + ((kq >> 1)*8 + (lane&7))*16;

    /* ---- prologue: Q + stage0 K; bias build ---- */
    #pragma unroll
    for (int i = 0; i < 2; i++) {
        int it2 = t + i*256;
        CPA16(sb + F_Q + it2*16, Qh + it2);
        CPA16(sb +       it2*16, Kh + it2);
    }
    CPA_COMMIT();
    #pragma unroll
    for (int i = 0; i < 16; i++) {
        int idx = t + i*256;
        bias[idx] = mrow[idx] ? 0.f : MASKF;
    }
    CPA_WAIT(0);
    __syncthreads();

    uint32_t qh[2][4];
    q_frags(sb + F_Q, wr, lane, qh);

    /* ---- phase 1: row sums (K-only 3-stage ring) ---- */
    float sum0 = 0.f, sum1 = 0.f;
    int stg_rd = 0;

    for (int kt = 0; kt < NKT; kt++) {
        if (kt + 1 < NKT) {
            int stw = stg_rd + 1; if (stw == 3) stw = 0;
            uint32_t st = sb + stw*F_STGSZ;
            const uint4* src = Kh + (size_t)(kt+1)*TILE_U4;
            CPA16(st + t*16, src + t);
            CPA16(st + (t+256)*16, src + t + 256);
        }
        CPA_COMMIT();
        CPA_WAIT(1);
        __syncthreads();

        uint32_t kb = sb + stg_rd*F_STGSZ + koff;
        const float* bk = bias + kt*TK;

        #pragma unroll 8
        for (int pj = 0; pj < 8; pj++) {
            uint32_t k0[4], k1[4];
            LDMX4(k0, kb + (pj*2)*128);
            LDMX4(k1, kb + (pj*2+1)*128);
            float c0[4] = {0.f,0.f,0.f,0.f};
            float c1[4] = {0.f,0.f,0.f,0.f};
            mma_f16(c0, qh[0], k0);
            mma_f16(c1, qh[0], k1);
            mma_f16(c0, qh[1], k0 + 2);
            mma_f16(c1, qh[1], k1 + 2);

            float2 ba = *(const float2*)&bk[pj*16 + cp];
            float2 bb = *(const float2*)&bk[pj*16 + 8 + cp];
            sum0 += ex2a(fmaf(c0[0], C1, ba.x)) + ex2a(fmaf(c0[1], C1, ba.y))
                  + ex2a(fmaf(c1[0], C1, bb.x)) + ex2a(fmaf(c1[1], C1, bb.y));
            sum1 += ex2a(fmaf(c0[2], C1, ba.x)) + ex2a(fmaf(c0[3], C1, ba.y))
                  + ex2a(fmaf(c1[2], C1, bb.x)) + ex2a(fmaf(c1[3], C1, bb.y));
        }
        if (++stg_rd == 3) stg_rd = 0;
    }
    __syncthreads();                 /* all phase-1 reads done before stage0 reuse */

    /* phase-2 prologue issued early, overlaps the reduction */
    #pragma unroll
    for (int i = 0; i < 2; i++) {
        int it2 = t + i*256;
        CPA16(sb +        it2*16, Kh + it2);
        CPA16(sb + 8192 + it2*16, Vt + it2);
    }
    CPA_COMMIT();

    sum0 += __shfl_xor_sync(0xffffffffu, sum0, 1);
    sum0 += __shfl_xor_sync(0xffffffffu, sum0, 2);
    sum1 += __shfl_xor_sync(0xffffffffu, sum1, 1);
    sum1 += __shfl_xor_sync(0xffffffffu, sum1, 2);
    float nls0 = -__log2f(sum0);
    float nls1 = -__log2f(sum1);

    /* ---- phase 2: recompute S, write attn_w, P@V ---- */
    float o[4][4];
    #pragma unroll
    for (int jd = 0; jd < 4; jd++)
        #pragma unroll
        for (int i = 0; i < 4; i++) o[jd][i] = 0.f;

    float* Arow0 = Ag ? Ag + (size_t)(qr0 + wr + gid)*L_S : (float*)0;
    float* Arow1 = Ag ? Ag + (size_t)(qr0 + wr + gid + 8)*L_S : (float*)0;

    stg_rd = 0;
    for (int kt = 0; kt < NKT; kt++) {
        if (kt + 1 < NKT) {
            int stw = stg_rd + 1; if (stw == 3) stw = 0;
            uint32_t st = sb + stw*F_STGSZ;
            size_t ti = (size_t)(kt+1)*TILE_U4;
            #pragma unroll
            for (int i = 0; i < 2; i++) {
                int it2 = t + i*256;
                CPA16(st + it2*16,        Kh + ti + it2);
                CPA16(st + 8192 + it2*16, Vt + ti + it2);
            }
        }
        CPA_COMMIT();
        CPA_WAIT(1);
        __syncthreads();

        uint32_t stg = sb + stg_rd*F_STGSZ;
        uint32_t kbh = stg + koff;
        uint32_t vb0 = stg + 8192 + voff;
        const float* bk = bias + kt*TK;
        float* a0 = Arow0 ? Arow0 + kt*TK + cp : (float*)0;
        float* a1 = Arow1 ? Arow1 + kt*TK + cp : (float*)0;

        #pragma unroll 4
        for (int pj = 0; pj < 8; pj++) {
            uint32_t k0[4], k1[4];
            LDMX4(k0, kbh + (pj*2)*128);
            LDMX4(k1, kbh + (pj*2+1)*128);

            float c0[4] = {0.f,0.f,0.f,0.f};
            float c1[4] = {0.f,0.f,0.f,0.f};
            mma_f16(c0, qh[0], k0);
            mma_f16(c1, qh[0], k1);
            mma_f16(c0, qh[1], k0 + 2);
            mma_f16(c1, qh[1], k1 + 2);

            float2 ba = *(const float2*)&bk[pj*16 + cp];
            float2 bb = *(const float2*)&bk[pj*16 + 8 + cp];
            float p0 = ex2a(fmaf(c0[0], C1, nls0 + ba.x));
            float p1 = ex2a(fmaf(c0[1], C1, nls0 + ba.y));
            float p2 = ex2a(fmaf(c0[2], C1, nls1 + ba.x));
            float p3 = ex2a(fmaf(c0[3], C1, nls1 + ba.y));
            float p4 = ex2a(fmaf(c1[0], C1, nls0 + bb.x));
            float p5 = ex2a(fmaf(c1[1], C1, nls0 + bb.y));
            float p6 = ex2a(fmaf(c1[2], C1, nls1 + bb.x));
            float p7 = ex2a(fmaf(c1[3], C1, nls1 + bb.y));

            if (write_attn) {
                /* streaming stores: keep attn_w out of L2 (evict-first) */
                __stcs((float2*)&a0[pj*16],     make_float2(p0, p1));
                __stcs((float2*)&a1[pj*16],     make_float2(p2, p3));
                __stcs((float2*)&a0[pj*16 + 8], make_float2(p4, p5));
                __stcs((float2*)&a1[pj*16 + 8], make_float2(p6, p7));
            }

            uint32_t ah[4];
            ah[0] = h2bits(__floats2half2_rn(p0, p1));
            ah[1] = h2bits(__floats2half2_rn(p2, p3));
            ah[2] = h2bits(__floats2half2_rn(p4, p5));
            ah[3] = h2bits(__floats2half2_rn(p6, p7));

            uint32_t va[4], vb2[4];
            LDMX4(va,  vb0 + (2*pj)*PSV);
            LDMX4(vb2, vb0 + (2*pj)*PSV + 256);

            mma_f16(o[0], ah, va);
            mma_f16(o[1], ah, va + 2);
            mma_f16(o[2], ah, vb2);
            mma_f16(o[3], ah, vb2 + 2);
        }
        if (++stg_rd == 3) stg_rd = 0;
    }

    float* Og0 = g_O + (size_t)(nh*L_S + qr0 + wr + gid)*D_H;
    float* Og1 = g_O + (size_t)(nh*L_S + qr0 + wr + gid + 8)*D_H;
    #pragma unroll
    for (int jd = 0; jd < 4; jd++) {
        int col = jd*8 + cp;
        __stcs((float2*)&Og0[col], make_float2(o[jd][0], o[jd][1]));
        __stcs((float2*)&Og1[col], make_float2(o[jd][2], o[jd][3]));
    }
}

/* ------- kernel 3: out = concat(O) @ Wo^T + bo (register-tiled) ------- */
#define OP_PITCH 132
__global__ __launch_bounds__(256) void outproj_kernel(const float* __restrict__ Wo,
                                                      const float* __restrict__ bo,
                                                      float* __restrict__ out)
{
    __shared__ float Xs[64*OP_PITCH];
    __shared__ float Wsm[64*OP_PITCH];
    int t = threadIdx.x;
    int row0 = blockIdx.x * 64;
    int eg = t & 7;
    int rt = t >> 3;

    for (int idx = t; idx < 64*32; idx += 256) {
        int r = idx >> 5, c4 = idx & 31;
        int row = row0 + r;
        int n = row >> 12, l = row & 4095;
        int f0 = c4*4;
        float4 v = make_float4(
            g_O[(((size_t)n*H_N + (f0>>5))*L_S + l)*D_H + (f0 & 31)],
            g_O[(((size_t)n*H_N + ((f0+1)>>5))*L_S + l)*D_H + ((f0+1) & 31)],
            g_O[(((size_t)n*H_N + ((f0+2)>>5))*L_S + l)*D_H + ((f0+2) & 31)],
            g_O[(((size_t)n*H_N + ((f0+3)>>5))*L_S + l)*D_H + ((f0+3) & 31)]);
        *(float4*)&Xs[r*OP_PITCH + f0] = v;
    }

    for (int et = 0; et < 2; et++) {
        __syncthreads();
        for (int idx = t; idx < 64*32; idx += 256) {
            int e = idx >> 5, c4 = idx & 31;
            *(float4*)&Wsm[e*OP_PITCH + c4*4] =
                *(const float4*)&Wo[(size_t)(et*64 + e)*EMB + c4*4];
        }
        __syncthreads();

        float acc[2][8];
        #pragma unroll
        for (int r = 0; r < 2; r++)
            #pragma unroll
            for (int j = 0; j < 8; j++) acc[r][j] = 0.f;

        const float* x0 = &Xs[(rt*2)*OP_PITCH];
        const float* x1 = &Xs[(rt*2+1)*OP_PITCH];
        #pragma unroll 4
        for (int f = 0; f < EMB; f++) {
            float a0 = x0[f], a1 = x1[f];
            #pragma unroll
            for (int j = 0; j < 8; j++) {
                float wv = Wsm[(j*8 + eg)*OP_PITCH + f];
                acc[0][j] += a0 * wv;
                acc[1][j] += a1 * wv;
            }
        }

        #pragma unroll
        for (int r = 0; r < 2; r++) {
            int row = row0 + rt*2 + r;
            #pragma unroll
            for (int j = 0; j < 8; j++) {
                int e = et*64 + j*8 + eg;
                out[(size_t)row*EMB + e] = acc[r][j] + bo[e];
            }
        }
    }
}

/* ---------------- launch ---------------- */
extern "C" void kernel_launch(void* const* d_in, const int* in_sizes, int n_in,
                              void* d_out, int out_size)
{
    const float* values = (const float*)d_in[0];
    const float* keys   = (const float*)d_in[1];
    const float* query  = (const float*)d_in[2];
    const int*   mask   = (const int*)d_in[3];
    const float* Wv     = (const float*)d_in[4];
    const float* Wk     = (const float*)d_in[5];
    const float* Wq     = (const float*)d_in[6];
    const float* Wo     = (const float*)d_in[7];
    const float* bo     = (const float*)d_in[8];
    float* out = (float*)d_out;

    const long long out_elems  = (long long)N_B * L_S * EMB;
    const long long attn_elems = (long long)N_B * H_N * L_S * L_S;
    int has_attn = ((long long)out_size >= out_elems + attn_elems);
    float* attn_out = has_attn ? (out + out_elems) : (float*)0;

    cudaFuncSetAttribute(fused_kernel, cudaFuncAttributeMaxDynamicSharedMemorySize, SMEM_FUSED);

    dim3 gc(NKT, NH, 3);
    projconv_kernel<<<gc, 256>>>(values, keys, query, Wv, Wk, Wq);

    dim3 g(L_S/TM, NH);
    fused_kernel<<<g, 256, SMEM_FUSED>>>(mask, attn_out, has_attn);

    outproj_kernel<<<(N_B*L_S)/64, 256>>>(Wo, bo, out);
}